// round 8
// baseline (speedup 1.0000x reference)
#include <cuda_runtime.h>
#include <cuda_fp16.h>
#include <cstdint>

#define BATCH 4
#define SEQ   4096
#define DIN   128
#define DOUT  64
#define BQ    128          // per CTA (two groups of 64)
#define BK    64
#define NTILES (SEQ / BK)  // 64

// Q pre-scale: 1/sqrt(64) * log2(e)  (softmax runs in exp2 domain)
#define QSCALE 0.1803368801111244f

// ---- fp16 scratch — device globals, no allocation ----
__device__ __half g_qh[BATCH * SEQ * DOUT];
__device__ __half g_ql[BATCH * SEQ * DOUT];
__device__ __half g_kh[BATCH * SEQ * DOUT];
__device__ __half g_kl[BATCH * SEQ * DOUT];
__device__ __half g_vt[BATCH * DOUT * SEQ];   // transposed: [b][dout][seq]

// ---- per-group smem (rows padded to 144B; 144%128=16 -> ldmatrix conflict-free) ----
#define G_QH    0
#define G_QL    9216
#define G_ST(s) (18432 + (s) * 27648)
#define G_KH(s) (G_ST(s))
#define G_KL(s) (G_ST(s) + 9216)
#define G_VT(s) (G_ST(s) + 18432)
#define GRP_BYTES 101376
#define SMEM_BYTES (2 * GRP_BYTES)      // 202752

typedef unsigned long long u64;

__device__ __forceinline__ uint32_t smem_u32(const void* p) {
    uint32_t a;
    asm("{ .reg .u64 t; cvta.to.shared.u64 t, %1; cvt.u32.u64 %0, t; }" : "=r"(a) : "l"(p));
    return a;
}
__device__ __forceinline__ void cp16(uint32_t dst, const void* src) {
    asm volatile("cp.async.cg.shared.global [%0], [%1], 16;" :: "r"(dst), "l"(src));
}
#define CP_COMMIT() asm volatile("cp.async.commit_group;" ::: "memory")
#define CP_WAIT1()  asm volatile("cp.async.wait_group 1;" ::: "memory")
#define BARG(id)    asm volatile("bar.sync %0, 128;" :: "r"(id) : "memory")

__device__ __forceinline__ float ex2f(float x) {
    float r; asm("ex2.approx.ftz.f32 %0, %1;" : "=f"(r) : "f"(x)); return r;
}

#define MMA16816(c, a0, a1, a2, a3, b0, b1) \
    asm volatile("mma.sync.aligned.m16n8k16.row.col.f32.f16.f16.f32 " \
                 "{%0,%1,%2,%3}, {%4,%5,%6,%7}, {%8,%9}, {%0,%1,%2,%3};" \
                 : "+f"((c)[0]), "+f"((c)[1]), "+f"((c)[2]), "+f"((c)[3]) \
                 : "r"(a0), "r"(a1), "r"(a2), "r"(a3), "r"(b0), "r"(b1))

#define LDMX4(r0, r1, r2, r3, a) \
    asm volatile("ldmatrix.sync.aligned.m8n8.x4.shared.b16 {%0,%1,%2,%3}, [%4];" \
                 : "=r"(r0), "=r"(r1), "=r"(r2), "=r"(r3) : "r"(a))

// ---- packed f32x2 ----
__device__ __forceinline__ u64 pk2(float lo, float hi) {
    u64 r; asm("mov.b64 %0, {%1, %2};" : "=l"(r) : "f"(lo), "f"(hi)); return r;
}
__device__ __forceinline__ void fma2(u64& d, u64 a, u64 b) {
    asm("fma.rn.f32x2 %0, %1, %2, %0;" : "+l"(d) : "l"(a), "l"(b));
}
__device__ __forceinline__ void upk2(u64 v, float& lo, float& hi) {
    asm("mov.b64 {%0, %1}, %2;" : "=f"(lo), "=f"(hi) : "l"(v));
}

// ---------------------------------------------------------------------------
// Kernel 1: QKV projection (unchanged from R6).
// ---------------------------------------------------------------------------
#define XS2_PAD  132
#define VTS_PAD  132
#define QKV_XS_B 0
#define QKV_VT_B 135168
#define QKV_SMEM 152064

__global__ __launch_bounds__(256)
void qkv_proj_kernel(const float* __restrict__ x,
                     const float* __restrict__ w) {
    extern __shared__ __align__(16) char qsm[];
    u64*    xs2 = (u64*)(qsm + QKV_XS_B);
    __half* vts = (__half*)(qsm + QKV_VT_B);

    const int b   = blockIdx.y;
    const int n0  = blockIdx.x * 128;
    const int tid = threadIdx.x;

    const float* xg = x + ((size_t)(b * SEQ + n0)) * DIN;
#pragma unroll
    for (int i = 0; i < 16; i++) {
        const int id4 = tid + i * 256;
        const int tok = id4 >> 5, c4 = (id4 & 31) << 2;
        const float4 v = *(const float4*)&xg[tok * DIN + c4];
        u64* dst = &xs2[tok * XS2_PAD + c4];
        dst[0] = pk2(v.x, v.x); dst[1] = pk2(v.y, v.y);
        dst[2] = pk2(v.z, v.z); dst[3] = pk2(v.w, v.w);
    }
    __syncthreads();

    const int tx = tid & 31, ty = tid >> 5;
    const int tok0 = ty * 16;

    u64 acc[16][3];
#pragma unroll
    for (int t = 0; t < 16; t++)
#pragma unroll
        for (int p = 0; p < 3; p++) acc[t][p] = 0ull;

#pragma unroll 2
    for (int d = 0; d < DIN; d++) {
        const u64 wq = pk2(w[(0 * DIN + d) * DOUT + tx], w[(0 * DIN + d) * DOUT + tx + 32]);
        const u64 wk = pk2(w[(1 * DIN + d) * DOUT + tx], w[(1 * DIN + d) * DOUT + tx + 32]);
        const u64 wv = pk2(w[(2 * DIN + d) * DOUT + tx], w[(2 * DIN + d) * DOUT + tx + 32]);
#pragma unroll
        for (int t = 0; t < 16; t++) {
            const u64 x2 = xs2[(tok0 + t) * XS2_PAD + d];
            fma2(acc[t][0], x2, wq);
            fma2(acc[t][1], x2, wk);
            fma2(acc[t][2], x2, wv);
        }
    }

#pragma unroll
    for (int t = 0; t < 16; t++) {
        const size_t row = (size_t)(b * SEQ + n0 + tok0 + t) * DOUT;
        float v0, v1;
        upk2(acc[t][0], v0, v1);
        v0 *= QSCALE; v1 *= QSCALE;
        __half h0 = __float2half_rn(v0), h1 = __float2half_rn(v1);
        g_qh[row + tx]      = h0; g_ql[row + tx]      = __float2half_rn(v0 - __half2float(h0));
        g_qh[row + tx + 32] = h1; g_ql[row + tx + 32] = __float2half_rn(v1 - __half2float(h1));
        upk2(acc[t][1], v0, v1);
        h0 = __float2half_rn(v0); h1 = __float2half_rn(v1);
        g_kh[row + tx]      = h0; g_kl[row + tx]      = __float2half_rn(v0 - __half2float(h0));
        g_kh[row + tx + 32] = h1; g_kl[row + tx + 32] = __float2half_rn(v1 - __half2float(h1));
        upk2(acc[t][2], v0, v1);
        vts[tx * VTS_PAD + tok0 + t]        = __float2half_rn(v0);
        vts[(tx + 32) * VTS_PAD + tok0 + t] = __float2half_rn(v1);
    }
    __syncthreads();

    const int e = tid >> 2, seg = tid & 3;
    const u64* srcv = (const u64*)(vts + e * VTS_PAD + seg * 32);
    uint4* dstv = (uint4*)&g_vt[(((size_t)(b * DOUT + e)) << 12) + n0 + seg * 32];
    u64 r[8];
#pragma unroll
    for (int k = 0; k < 8; k++) r[k] = srcv[k];
#pragma unroll
    for (int k = 0; k < 4; k++)
        dstv[k] = make_uint4((uint32_t)r[2*k], (uint32_t)(r[2*k] >> 32),
                             (uint32_t)r[2*k+1], (uint32_t)(r[2*k+1] >> 32));
}

// ---------------------------------------------------------------------------
// Kernel 2: flash attention, two independent 4-warp groups (anti-phase).
// ---------------------------------------------------------------------------
__device__ __forceinline__ void load_kv_g(uint32_t gb, int stg,
                                          int b, int kt, int gtid) {
    const __half* kh = g_kh + ((size_t)(b * SEQ + kt)) * DOUT;
    const __half* kl = g_kl + ((size_t)(b * SEQ + kt)) * DOUT;
    const __half* vt = g_vt + (((size_t)b * DOUT) << 12) + kt;
#pragma unroll
    for (int i = 0; i < 4; i++) {
        const int id = gtid + i * 128;          // 0..511
        const int row = id >> 3, c = id & 7;    // 64 rows x 8 chunks
        cp16(gb + G_KH(stg) + row * 144 + c * 16, kh + row * DOUT + c * 8);
        cp16(gb + G_KL(stg) + row * 144 + c * 16, kl + row * DOUT + c * 8);
        cp16(gb + G_VT(stg) + row * 144 + c * 16, vt + ((size_t)row << 12) + c * 8);
    }
}

__global__ __launch_bounds__(256, 1)
void attn_kernel(float* __restrict__ out) {
    extern __shared__ __align__(128) char sm[];
    const uint32_t smb = smem_u32(sm);
    const int tid  = threadIdx.x;
    const int wid  = tid >> 5;
    const int lane = tid & 31;
    const int g    = lane >> 2;
    const int tq   = lane & 3;
    const int grp  = wid >> 2;           // warpgroup 0/1
    const int gwid = wid & 3;
    const int gtid = tid & 127;
    const int b    = blockIdx.y;
    const int q0   = blockIdx.x * BQ + grp * 64;
    const int r0g  = gwid * 16;
    const uint32_t gb = smb + (uint32_t)grp * GRP_BYTES;
    const int bar  = grp + 1;
    const int trot = grp << 5;           // group 1 starts at tile 32

    const int lt = lane >> 3, lr = lane & 7;
    const uint32_t aoff = (uint32_t)((r0g + ((lt & 1) << 3) + lr) * 144 + ((lt >> 1) << 4));
    const uint32_t boff = (uint32_t)((((lane >> 4) << 3) + lr) * 144 + ((lt & 1) << 4));

    // ---- prologue: group Q + stages 0,1 ----
    {
        const __half* qh = g_qh + ((size_t)(b * SEQ + q0)) * DOUT;
        const __half* ql = g_ql + ((size_t)(b * SEQ + q0)) * DOUT;
#pragma unroll
        for (int i = 0; i < 4; i++) {
            const int id = gtid + i * 128;
            const int row = id >> 3, c = id & 7;
            cp16(gb + G_QH + row * 144 + c * 16, qh + row * DOUT + c * 8);
            cp16(gb + G_QL + row * 144 + c * 16, ql + row * DOUT + c * 8);
        }
        load_kv_g(gb, 0, b, ((0 + trot) & 63) * BK, gtid);
        CP_COMMIT();
        load_kv_g(gb, 1, b, ((1 + trot) & 63) * BK, gtid);
        CP_COMMIT();
    }

    float o[8][4];
#pragma unroll
    for (int j = 0; j < 8; j++)
#pragma unroll
        for (int k = 0; k < 4; k++) o[j][k] = 0.f;
    float m0 = -3.0e38f, m1 = -3.0e38f, l0 = 0.f, l1 = 0.f;

    for (int t = 0; t < NTILES; t++) {
        CP_WAIT1();
        BARG(bar);
        if (t + 2 < NTILES)
            load_kv_g(gb, (t + 2) % 3, b, ((t + 2 + trot) & 63) * BK, gtid);
        CP_COMMIT();

        const int stg = t % 3;
        const uint32_t khb = gb + G_KH(stg) + boff;
        const uint32_t klb = gb + G_KL(stg) + boff;
        const uint32_t vtb = gb + G_VT(stg) + boff;

        // ---- QK^T: 16 x 64, 3-pass split-fp16 ----
        float s[8][4];
#pragma unroll
        for (int j = 0; j < 8; j++)
#pragma unroll
            for (int k = 0; k < 4; k++) s[j][k] = 0.f;

#pragma unroll
        for (int ks = 0; ks < 4; ks++) {
            uint32_t ah0, ah1, ah2, ah3, al0, al1, al2, al3;
            LDMX4(ah0, ah1, ah2, ah3, gb + G_QH + aoff + ks * 32);
            LDMX4(al0, al1, al2, al3, gb + G_QL + aoff + ks * 32);
#pragma unroll
            for (int jp = 0; jp < 4; jp++) {
                uint32_t bh0, bh1, bh2, bh3, bl0, bl1, bl2, bl3;
                LDMX4(bh0, bh1, bh2, bh3, khb + jp * 2304 + ks * 32);
                LDMX4(bl0, bl1, bl2, bl3, klb + jp * 2304 + ks * 32);
                MMA16816(s[2*jp],   ah0, ah1, ah2, ah3, bh0, bh1);
                MMA16816(s[2*jp+1], ah0, ah1, ah2, ah3, bh2, bh3);
                MMA16816(s[2*jp],   ah0, ah1, ah2, ah3, bl0, bl1);
                MMA16816(s[2*jp+1], ah0, ah1, ah2, ah3, bl2, bl3);
                MMA16816(s[2*jp],   al0, al1, al2, al3, bh0, bh1);
                MMA16816(s[2*jp+1], al0, al1, al2, al3, bh2, bh3);
            }
        }

        // ---- online softmax (exp2 domain) ----
        float mx0 = -3.0e38f, mx1 = -3.0e38f;
#pragma unroll
        for (int j = 0; j < 8; j++) {
            mx0 = fmaxf(mx0, fmaxf(s[j][0], s[j][1]));
            mx1 = fmaxf(mx1, fmaxf(s[j][2], s[j][3]));
        }
        mx0 = fmaxf(mx0, __shfl_xor_sync(0xffffffffu, mx0, 1));
        mx0 = fmaxf(mx0, __shfl_xor_sync(0xffffffffu, mx0, 2));
        mx1 = fmaxf(mx1, __shfl_xor_sync(0xffffffffu, mx1, 1));
        mx1 = fmaxf(mx1, __shfl_xor_sync(0xffffffffu, mx1, 2));
        const float mn0 = fmaxf(m0, mx0), mn1 = fmaxf(m1, mx1);
        const float c0 = ex2f(m0 - mn0), c1 = ex2f(m1 - mn1);

        uint32_t pa[4][4];
        float rs0 = 0.f, rs1 = 0.f;
#pragma unroll
        for (int j = 0; j < 8; j++) {
            const float e0 = ex2f(s[j][0] - mn0), e1 = ex2f(s[j][1] - mn0);
            const float e2 = ex2f(s[j][2] - mn1), e3 = ex2f(s[j][3] - mn1);
            rs0 += e0 + e1;  rs1 += e2 + e3;
            const __half2 h01 = __floats2half2_rn(e0, e1);
            const __half2 h23 = __floats2half2_rn(e2, e3);
            pa[j >> 1][(j & 1) * 2 + 0] = *(const uint32_t*)&h01;
            pa[j >> 1][(j & 1) * 2 + 1] = *(const uint32_t*)&h23;
        }
        rs0 += __shfl_xor_sync(0xffffffffu, rs0, 1);
        rs0 += __shfl_xor_sync(0xffffffffu, rs0, 2);
        rs1 += __shfl_xor_sync(0xffffffffu, rs1, 1);
        rs1 += __shfl_xor_sync(0xffffffffu, rs1, 2);
        l0 = l0 * c0 + rs0;  m0 = mn0;
        l1 = l1 * c1 + rs1;  m1 = mn1;

        // ---- PV: rescale then o += P @ V ----
#pragma unroll
        for (int j = 0; j < 8; j++) {
            o[j][0] *= c0; o[j][1] *= c0;
            o[j][2] *= c1; o[j][3] *= c1;
        }
#pragma unroll
        for (int ks = 0; ks < 4; ks++) {
#pragma unroll
            for (int jp = 0; jp < 4; jp++) {
                uint32_t v0, v1, v2, v3;
                LDMX4(v0, v1, v2, v3, vtb + jp * 2304 + ks * 32);
                MMA16816(o[2*jp],   pa[ks][0], pa[ks][1], pa[ks][2], pa[ks][3], v0, v1);
                MMA16816(o[2*jp+1], pa[ks][0], pa[ks][1], pa[ks][2], pa[ks][3], v2, v3);
            }
        }
    }

    // ---- epilogue ----
    const float rl0 = __frcp_rn(l0), rl1 = __frcp_rn(l1);
    float* O = out + ((size_t)(b * SEQ + q0 + r0g + g)) * DOUT;
#pragma unroll
    for (int j = 0; j < 8; j++) {
        const int col = j * 8 + 2 * tq;
        *(float2*)&O[col]            = make_float2(o[j][0] * rl0, o[j][1] * rl0);
        *(float2*)&O[8 * DOUT + col] = make_float2(o[j][2] * rl1, o[j][3] * rl1);
    }
}

// ---------------------------------------------------------------------------
extern "C" void kernel_launch(void* const* d_in, const int* in_sizes, int n_in,
                              void* d_out, int out_size) {
    const float* x = (const float*)d_in[0];   // [4,4096,128]
    const float* w = (const float*)d_in[1];   // [3,128,64]
    float* out = (float*)d_out;               // [4,4096,64]

    cudaFuncSetAttribute(attn_kernel,
                         cudaFuncAttributeMaxDynamicSharedMemorySize, SMEM_BYTES);
    cudaFuncSetAttribute(qkv_proj_kernel,
                         cudaFuncAttributeMaxDynamicSharedMemorySize, QKV_SMEM);

    qkv_proj_kernel<<<dim3(SEQ / 128, BATCH), 256, QKV_SMEM>>>(x, w);
    attn_kernel<<<dim3(SEQ / BQ, BATCH), 256, SMEM_BYTES>>>(out);
}

// round 9
// speedup vs baseline: 1.2060x; 1.2060x over previous
#include <cuda_runtime.h>
#include <cuda_fp16.h>
#include <cstdint>

#define BATCH 4
#define SEQ   4096
#define DIN   128
#define DOUT  64
#define BQ    128
#define BK    64
#define NTILES 32          // per key-half: 2048/64

// Q pre-scale: 1/sqrt(64) * log2(e)  (softmax runs in exp2 domain)
#define QSCALE 0.1803368801111244f

// ---- fp16 scratch — device globals, no allocation ----
__device__ __half g_qh[BATCH * SEQ * DOUT];
__device__ __half g_ql[BATCH * SEQ * DOUT];
__device__ __half g_kh[BATCH * SEQ * DOUT];
__device__ __half g_kl[BATCH * SEQ * DOUT];
__device__ __half g_vt[BATCH * DOUT * SEQ];   // transposed: [b][dout][seq]

// ---- attn smem ----
// Q: 128 rows x 144B (hi+lo). Per key-half: 3 stages x (kh+kl+vt) 27648B.
#define QH_B       0
#define QL_B       18432
#define KV_B(h, s) (36864 + (h) * 82944 + (s) * 27648)
#define KH_O       0
#define KL_O       9216
#define VT_O       18432
#define SMEM_BYTES 202752

typedef unsigned long long u64;

__device__ __forceinline__ uint32_t smem_u32(const void* p) {
    uint32_t a;
    asm("{ .reg .u64 t; cvta.to.shared.u64 t, %1; cvt.u32.u64 %0, t; }" : "=r"(a) : "l"(p));
    return a;
}
__device__ __forceinline__ void cp16(uint32_t dst, const void* src) {
    asm volatile("cp.async.cg.shared.global [%0], [%1], 16;" :: "r"(dst), "l"(src));
}
#define CP_COMMIT() asm volatile("cp.async.commit_group;" ::: "memory")
#define CP_WAIT1()  asm volatile("cp.async.wait_group 1;" ::: "memory")
#define CP_WAIT2()  asm volatile("cp.async.wait_group 2;" ::: "memory")
#define BARG(id)    asm volatile("bar.sync %0, 256;" :: "r"(id) : "memory")

__device__ __forceinline__ float ex2f(float x) {
    float r; asm("ex2.approx.ftz.f32 %0, %1;" : "=f"(r) : "f"(x)); return r;
}

#define MMA16816(c, a0, a1, a2, a3, b0, b1) \
    asm volatile("mma.sync.aligned.m16n8k16.row.col.f32.f16.f16.f32 " \
                 "{%0,%1,%2,%3}, {%4,%5,%6,%7}, {%8,%9}, {%0,%1,%2,%3};" \
                 : "+f"((c)[0]), "+f"((c)[1]), "+f"((c)[2]), "+f"((c)[3]) \
                 : "r"(a0), "r"(a1), "r"(a2), "r"(a3), "r"(b0), "r"(b1))

#define LDMX4(r0, r1, r2, r3, a) \
    asm volatile("ldmatrix.sync.aligned.m8n8.x4.shared.b16 {%0,%1,%2,%3}, [%4];" \
                 : "=r"(r0), "=r"(r1), "=r"(r2), "=r"(r3) : "r"(a))

// ---- packed f32x2 ----
__device__ __forceinline__ u64 pk2(float lo, float hi) {
    u64 r; asm("mov.b64 %0, {%1, %2};" : "=l"(r) : "f"(lo), "f"(hi)); return r;
}
__device__ __forceinline__ void fma2(u64& d, u64 a, u64 b) {
    asm("fma.rn.f32x2 %0, %1, %2, %0;" : "+l"(d) : "l"(a), "l"(b));
}
__device__ __forceinline__ void upk2(u64 v, float& lo, float& hi) {
    asm("mov.b64 {%0, %1}, %2;" : "=f"(lo), "=f"(hi) : "l"(v));
}

// ---------------------------------------------------------------------------
// Kernel 1: QKV projection (unchanged, best-known version).
// ---------------------------------------------------------------------------
#define XS2_PAD  132
#define VTS_PAD  132
#define QKV_XS_B 0
#define QKV_VT_B 135168
#define QKV_SMEM 152064

__global__ __launch_bounds__(256)
void qkv_proj_kernel(const float* __restrict__ x,
                     const float* __restrict__ w) {
    extern __shared__ __align__(16) char qsm[];
    u64*    xs2 = (u64*)(qsm + QKV_XS_B);
    __half* vts = (__half*)(qsm + QKV_VT_B);

    const int b   = blockIdx.y;
    const int n0  = blockIdx.x * 128;
    const int tid = threadIdx.x;

    const float* xg = x + ((size_t)(b * SEQ + n0)) * DIN;
#pragma unroll
    for (int i = 0; i < 16; i++) {
        const int id4 = tid + i * 256;
        const int tok = id4 >> 5, c4 = (id4 & 31) << 2;
        const float4 v = *(const float4*)&xg[tok * DIN + c4];
        u64* dst = &xs2[tok * XS2_PAD + c4];
        dst[0] = pk2(v.x, v.x); dst[1] = pk2(v.y, v.y);
        dst[2] = pk2(v.z, v.z); dst[3] = pk2(v.w, v.w);
    }
    __syncthreads();

    const int tx = tid & 31, ty = tid >> 5;
    const int tok0 = ty * 16;

    u64 acc[16][3];
#pragma unroll
    for (int t = 0; t < 16; t++)
#pragma unroll
        for (int p = 0; p < 3; p++) acc[t][p] = 0ull;

#pragma unroll 2
    for (int d = 0; d < DIN; d++) {
        const u64 wq = pk2(w[(0 * DIN + d) * DOUT + tx], w[(0 * DIN + d) * DOUT + tx + 32]);
        const u64 wk = pk2(w[(1 * DIN + d) * DOUT + tx], w[(1 * DIN + d) * DOUT + tx + 32]);
        const u64 wv = pk2(w[(2 * DIN + d) * DOUT + tx], w[(2 * DIN + d) * DOUT + tx + 32]);
#pragma unroll
        for (int t = 0; t < 16; t++) {
            const u64 x2 = xs2[(tok0 + t) * XS2_PAD + d];
            fma2(acc[t][0], x2, wq);
            fma2(acc[t][1], x2, wk);
            fma2(acc[t][2], x2, wv);
        }
    }

#pragma unroll
    for (int t = 0; t < 16; t++) {
        const size_t row = (size_t)(b * SEQ + n0 + tok0 + t) * DOUT;
        float v0, v1;
        upk2(acc[t][0], v0, v1);
        v0 *= QSCALE; v1 *= QSCALE;
        __half h0 = __float2half_rn(v0), h1 = __float2half_rn(v1);
        g_qh[row + tx]      = h0; g_ql[row + tx]      = __float2half_rn(v0 - __half2float(h0));
        g_qh[row + tx + 32] = h1; g_ql[row + tx + 32] = __float2half_rn(v1 - __half2float(h1));
        upk2(acc[t][1], v0, v1);
        h0 = __float2half_rn(v0); h1 = __float2half_rn(v1);
        g_kh[row + tx]      = h0; g_kl[row + tx]      = __float2half_rn(v0 - __half2float(h0));
        g_kh[row + tx + 32] = h1; g_kl[row + tx + 32] = __float2half_rn(v1 - __half2float(h1));
        upk2(acc[t][2], v0, v1);
        vts[tx * VTS_PAD + tok0 + t]        = __float2half_rn(v0);
        vts[(tx + 32) * VTS_PAD + tok0 + t] = __float2half_rn(v1);
    }
    __syncthreads();

    const int e = tid >> 2, seg = tid & 3;
    const u64* srcv = (const u64*)(vts + e * VTS_PAD + seg * 32);
    uint4* dstv = (uint4*)&g_vt[(((size_t)(b * DOUT + e)) << 12) + n0 + seg * 32];
    u64 r[8];
#pragma unroll
    for (int k = 0; k < 8; k++) r[k] = srcv[k];
#pragma unroll
    for (int k = 0; k < 4; k++)
        dstv[k] = make_uint4((uint32_t)r[2*k], (uint32_t)(r[2*k] >> 32),
                             (uint32_t)r[2*k+1], (uint32_t)(r[2*k+1] >> 32));
}

// ---------------------------------------------------------------------------
// Kernel 2: flash attention, 512 threads; warp pair = same 16 q-rows,
// disjoint key halves; split-softmax merge at epilogue.
// ---------------------------------------------------------------------------
__device__ __forceinline__ void load_kv_h(uint32_t kb, int b, int kt, int htid) {
    const __half* kh = g_kh + ((size_t)(b * SEQ + kt)) * DOUT;
    const __half* kl = g_kl + ((size_t)(b * SEQ + kt)) * DOUT;
    const __half* vt = g_vt + (((size_t)b * DOUT) << 12) + kt;
#pragma unroll
    for (int i = 0; i < 2; i++) {
        const int id = htid + i * 256;           // 0..511
        const int row = id >> 3, c = id & 7;     // 64 rows x 8 chunks
        cp16(kb + KH_O + row * 144 + c * 16, kh + row * DOUT + c * 8);
        cp16(kb + KL_O + row * 144 + c * 16, kl + row * DOUT + c * 8);
        cp16(kb + VT_O + row * 144 + c * 16, vt + ((size_t)row << 12) + c * 8);
    }
}

__global__ __launch_bounds__(512, 1)
void attn_kernel(float* __restrict__ out) {
    extern __shared__ __align__(128) char sm[];
    const uint32_t smb = smem_u32(sm);
    const int tid  = threadIdx.x;
    const int wid  = tid >> 5;
    const int lane = tid & 31;
    const int g    = lane >> 2;
    const int tq   = lane & 3;
    const int half = wid & 1;            // key half
    const int pair = wid >> 1;           // q-row group 0..7
    const int htid = pair * 32 + lane;   // 0..255 within half
    const int b    = blockIdx.y;
    const int q0   = blockIdx.x * BQ;
    const int r0   = pair * 16;
    const int k0   = half * 2048;

    const int lt = lane >> 3, lr = lane & 7;
    const uint32_t aoff = (uint32_t)((r0 + ((lt & 1) << 3) + lr) * 144 + ((lt >> 1) << 4));
    const uint32_t boff = (uint32_t)((((lane >> 4) << 3) + lr) * 144 + ((lt & 1) << 4));

    // ---- prologue: Q (group 0), stage0 (group 1), stage1 (group 2) ----
    {
        const __half* qh = g_qh + ((size_t)(b * SEQ + q0)) * DOUT;
        const __half* ql = g_ql + ((size_t)(b * SEQ + q0)) * DOUT;
#pragma unroll
        for (int i = 0; i < 2; i++) {
            const int id = tid + i * 512;
            const int row = id >> 3, c = id & 7;
            cp16(smb + QH_B + row * 144 + c * 16, qh + row * DOUT + c * 8);
            cp16(smb + QL_B + row * 144 + c * 16, ql + row * DOUT + c * 8);
        }
        CP_COMMIT();
        load_kv_h(smb + KV_B(half, 0), b, k0, htid);
        CP_COMMIT();
        load_kv_h(smb + KV_B(half, 1), b, k0 + BK, htid);
        CP_COMMIT();
    }
    CP_WAIT2();            // Q landed everywhere
    __syncthreads();       // all threads see Q

    float o[8][4];
#pragma unroll
    for (int j = 0; j < 8; j++)
#pragma unroll
        for (int k = 0; k < 4; k++) o[j][k] = 0.f;
    float m0 = -3.0e38f, m1 = -3.0e38f, l0 = 0.f, l1 = 0.f;

    for (int t = 0; t < NTILES; t++) {
        CP_WAIT1();
        BARG(1 + half);
        if (t + 2 < NTILES)
            load_kv_h(smb + KV_B(half, (t + 2) % 3), b, k0 + (t + 2) * BK, htid);
        CP_COMMIT();

        const uint32_t kvb = smb + KV_B(half, t % 3);
        const uint32_t khb = kvb + KH_O + boff;
        const uint32_t klb = kvb + KL_O + boff;
        const uint32_t vtb = kvb + VT_O + boff;

        // ---- QK^T: 16 x 64, 3-pass split-fp16 ----
        float s[8][4];
#pragma unroll
        for (int j = 0; j < 8; j++)
#pragma unroll
            for (int k = 0; k < 4; k++) s[j][k] = 0.f;

#pragma unroll
        for (int ks = 0; ks < 4; ks++) {
            uint32_t ah0, ah1, ah2, ah3, al0, al1, al2, al3;
            LDMX4(ah0, ah1, ah2, ah3, smb + QH_B + aoff + ks * 32);
            LDMX4(al0, al1, al2, al3, smb + QL_B + aoff + ks * 32);
#pragma unroll
            for (int jp = 0; jp < 4; jp++) {
                uint32_t bh0, bh1, bh2, bh3, bl0, bl1, bl2, bl3;
                LDMX4(bh0, bh1, bh2, bh3, khb + jp * 2304 + ks * 32);
                LDMX4(bl0, bl1, bl2, bl3, klb + jp * 2304 + ks * 32);
                MMA16816(s[2*jp],   ah0, ah1, ah2, ah3, bh0, bh1);
                MMA16816(s[2*jp+1], ah0, ah1, ah2, ah3, bh2, bh3);
                MMA16816(s[2*jp],   ah0, ah1, ah2, ah3, bl0, bl1);
                MMA16816(s[2*jp+1], ah0, ah1, ah2, ah3, bl2, bl3);
                MMA16816(s[2*jp],   al0, al1, al2, al3, bh0, bh1);
                MMA16816(s[2*jp+1], al0, al1, al2, al3, bh2, bh3);
            }
        }

        // ---- online softmax (exp2 domain) ----
        float mx0 = -3.0e38f, mx1 = -3.0e38f;
#pragma unroll
        for (int j = 0; j < 8; j++) {
            mx0 = fmaxf(mx0, fmaxf(s[j][0], s[j][1]));
            mx1 = fmaxf(mx1, fmaxf(s[j][2], s[j][3]));
        }
        mx0 = fmaxf(mx0, __shfl_xor_sync(0xffffffffu, mx0, 1));
        mx0 = fmaxf(mx0, __shfl_xor_sync(0xffffffffu, mx0, 2));
        mx1 = fmaxf(mx1, __shfl_xor_sync(0xffffffffu, mx1, 1));
        mx1 = fmaxf(mx1, __shfl_xor_sync(0xffffffffu, mx1, 2));
        const float mn0 = fmaxf(m0, mx0), mn1 = fmaxf(m1, mx1);
        const float c0 = ex2f(m0 - mn0), c1 = ex2f(m1 - mn1);

        uint32_t pa[4][4];
        float rs0 = 0.f, rs1 = 0.f;
#pragma unroll
        for (int j = 0; j < 8; j++) {
            const float e0 = ex2f(s[j][0] - mn0), e1 = ex2f(s[j][1] - mn0);
            const float e2 = ex2f(s[j][2] - mn1), e3 = ex2f(s[j][3] - mn1);
            rs0 += e0 + e1;  rs1 += e2 + e3;
            const __half2 h01 = __floats2half2_rn(e0, e1);
            const __half2 h23 = __floats2half2_rn(e2, e3);
            pa[j >> 1][(j & 1) * 2 + 0] = *(const uint32_t*)&h01;
            pa[j >> 1][(j & 1) * 2 + 1] = *(const uint32_t*)&h23;
        }
        rs0 += __shfl_xor_sync(0xffffffffu, rs0, 1);
        rs0 += __shfl_xor_sync(0xffffffffu, rs0, 2);
        rs1 += __shfl_xor_sync(0xffffffffu, rs1, 1);
        rs1 += __shfl_xor_sync(0xffffffffu, rs1, 2);
        l0 = l0 * c0 + rs0;  m0 = mn0;
        l1 = l1 * c1 + rs1;  m1 = mn1;

        // ---- PV: rescale then o += P @ V ----
#pragma unroll
        for (int j = 0; j < 8; j++) {
            o[j][0] *= c0; o[j][1] *= c0;
            o[j][2] *= c1; o[j][3] *= c1;
        }
#pragma unroll
        for (int ks = 0; ks < 4; ks++) {
#pragma unroll
            for (int jp = 0; jp < 4; jp++) {
                uint32_t v0, v1, v2, v3;
                LDMX4(v0, v1, v2, v3, vtb + jp * 2304 + ks * 32);
                MMA16816(o[2*jp],   pa[ks][0], pa[ks][1], pa[ks][2], pa[ks][3], v0, v1);
                MMA16816(o[2*jp+1], pa[ks][0], pa[ks][1], pa[ks][2], pa[ks][3], v2, v3);
            }
        }
    }

    // ---- split-softmax merge: odd half publishes, even half combines ----
    __syncthreads();
    float* xo = (float*)sm;                     // [pair][16][68] floats
    float* xm = (float*)(sm + 8 * 16 * 68 * 4); // [pair*16+row][2] = m, l

    if (half == 1) {
#pragma unroll
        for (int j = 0; j < 8; j++) {
            const int col = j * 8 + 2 * tq;
            *(float2*)&xo[(r0 + g) * 68 + col]     = make_float2(o[j][0], o[j][1]);
            *(float2*)&xo[(r0 + g + 8) * 68 + col] = make_float2(o[j][2], o[j][3]);
        }
        if (tq == 0) {
            xm[(r0 + g) * 2]         = m0;  xm[(r0 + g) * 2 + 1]     = l0;
            xm[(r0 + g + 8) * 2]     = m1;  xm[(r0 + g + 8) * 2 + 1] = l1;
        }
    }
    __syncthreads();

    if (half == 0) {
        const float mo0 = xm[(r0 + g) * 2],     lo0 = xm[(r0 + g) * 2 + 1];
        const float mo1 = xm[(r0 + g + 8) * 2], lo1 = xm[(r0 + g + 8) * 2 + 1];
        const float mm0 = fmaxf(m0, mo0), mm1 = fmaxf(m1, mo1);
        const float ce0 = ex2f(m0 - mm0), co0 = ex2f(mo0 - mm0);
        const float ce1 = ex2f(m1 - mm1), co1 = ex2f(mo1 - mm1);
        const float rl0 = __frcp_rn(l0 * ce0 + lo0 * co0);
        const float rl1 = __frcp_rn(l1 * ce1 + lo1 * co1);

        float* O = out + ((size_t)(b * SEQ + q0 + r0 + g)) * DOUT;
#pragma unroll
        for (int j = 0; j < 8; j++) {
            const int col = j * 8 + 2 * tq;
            const float2 q0v = *(const float2*)&xo[(r0 + g) * 68 + col];
            const float2 q1v = *(const float2*)&xo[(r0 + g + 8) * 68 + col];
            *(float2*)&O[col] = make_float2(
                (o[j][0] * ce0 + q0v.x * co0) * rl0,
                (o[j][1] * ce0 + q0v.y * co0) * rl0);
            *(float2*)&O[8 * DOUT + col] = make_float2(
                (o[j][2] * ce1 + q1v.x * co1) * rl1,
                (o[j][3] * ce1 + q1v.y * co1) * rl1);
        }
    }
}

// ---------------------------------------------------------------------------
extern "C" void kernel_launch(void* const* d_in, const int* in_sizes, int n_in,
                              void* d_out, int out_size) {
    const float* x = (const float*)d_in[0];   // [4,4096,128]
    const float* w = (const float*)d_in[1];   // [3,128,64]
    float* out = (float*)d_out;               // [4,4096,64]

    cudaFuncSetAttribute(attn_kernel,
                         cudaFuncAttributeMaxDynamicSharedMemorySize, SMEM_BYTES);
    cudaFuncSetAttribute(qkv_proj_kernel,
                         cudaFuncAttributeMaxDynamicSharedMemorySize, QKV_SMEM);

    qkv_proj_kernel<<<dim3(SEQ / 128, BATCH), 256, QKV_SMEM>>>(x, w);
    attn_kernel<<<dim3(SEQ / BQ, BATCH), 512, SMEM_BYTES>>>(out);
}

// round 10
// speedup vs baseline: 1.3030x; 1.0804x over previous
#include <cuda_runtime.h>
#include <cuda_fp16.h>
#include <cstdint>

#define BATCH 4
#define SEQ   4096
#define DIN   128
#define DOUT  64
#define BQ    128
#define BK    64
#define NTILES 32          // per key-half: 2048/64

// Q pre-scale: 1/sqrt(64) * log2(e)  (softmax runs in exp2 domain)
#define QSCALE 0.1803368801111244f

// ---- fp16 scratch — device globals, no allocation ----
__device__ __half g_qh[BATCH * SEQ * DOUT];
__device__ __half g_ql[BATCH * SEQ * DOUT];
__device__ __half g_kh[BATCH * SEQ * DOUT];
__device__ __half g_kl[BATCH * SEQ * DOUT];
__device__ __half g_vt[BATCH * DOUT * SEQ];   // transposed: [b][dout][seq]

// ---- attn smem ----
#define QH_B       0
#define QL_B       18432
#define KV_B(h, s) (36864 + (h) * 82944 + (s) * 27648)
#define KH_O       0
#define KL_O       9216
#define VT_O       18432
#define SMEM_BYTES 202752

typedef unsigned long long u64;

__device__ __forceinline__ uint32_t smem_u32(const void* p) {
    uint32_t a;
    asm("{ .reg .u64 t; cvta.to.shared.u64 t, %1; cvt.u32.u64 %0, t; }" : "=r"(a) : "l"(p));
    return a;
}
__device__ __forceinline__ void cp16(uint32_t dst, const void* src) {
    asm volatile("cp.async.cg.shared.global [%0], [%1], 16;" :: "r"(dst), "l"(src));
}
#define CP_COMMIT() asm volatile("cp.async.commit_group;" ::: "memory")
#define CP_WAIT1()  asm volatile("cp.async.wait_group 1;" ::: "memory")
#define CP_WAIT2()  asm volatile("cp.async.wait_group 2;" ::: "memory")
#define BARG(id)    asm volatile("bar.sync %0, 256;" :: "r"(id) : "memory")

__device__ __forceinline__ float ex2f(float x) {
    float r; asm("ex2.approx.ftz.f32 %0, %1;" : "=f"(r) : "f"(x)); return r;
}

#define MMA16816(c, a0, a1, a2, a3, b0, b1) \
    asm volatile("mma.sync.aligned.m16n8k16.row.col.f32.f16.f16.f32 " \
                 "{%0,%1,%2,%3}, {%4,%5,%6,%7}, {%8,%9}, {%0,%1,%2,%3};" \
                 : "+f"((c)[0]), "+f"((c)[1]), "+f"((c)[2]), "+f"((c)[3]) \
                 : "r"(a0), "r"(a1), "r"(a2), "r"(a3), "r"(b0), "r"(b1))

#define LDMX4(r0, r1, r2, r3, a) \
    asm volatile("ldmatrix.sync.aligned.m8n8.x4.shared.b16 {%0,%1,%2,%3}, [%4];" \
                 : "=r"(r0), "=r"(r1), "=r"(r2), "=r"(r3) : "r"(a))

// ---- packed f32x2 ----
__device__ __forceinline__ u64 pk2(float lo, float hi) {
    u64 r; asm("mov.b64 %0, {%1, %2};" : "=l"(r) : "f"(lo), "f"(hi)); return r;
}
__device__ __forceinline__ void fma2(u64& d, u64 a, u64 b) {
    asm("fma.rn.f32x2 %0, %1, %2, %0;" : "+l"(d) : "l"(a), "l"(b));
}
__device__ __forceinline__ void upk2(u64 v, float& lo, float& hi) {
    asm("mov.b64 {%0, %1}, %2;" : "=f"(lo), "=f"(hi) : "l"(v));
}

// ---------------------------------------------------------------------------
// Kernel 1: QKV projection. 512 threads, 8 tokens/thread. w staged in smem
// pre-packed as f32x2 pairs (e, e+32) -> zero LDG in the inner loop.
// ---------------------------------------------------------------------------
#define XS_PAD   132                     // floats per x row
#define VTS_PAD  136                     // halves per vts row (272B, 16B-aligned)
#define QKV_W_B  0                       // [3][128][32] u64 = 98304
#define QKV_XS_B 98304                   // 128*132*4 = 67584
#define QKV_VT_B 165888                  // 64*136*2  = 17408
#define QKV_SMEM 183296

__global__ __launch_bounds__(512)
void qkv_proj_kernel(const float* __restrict__ x,
                     const float* __restrict__ w) {
    extern __shared__ __align__(16) char qsm[];
    u64*    wp2 = (u64*)(qsm + QKV_W_B);        // [p][d][tx] packed pairs
    float*  xs  = (float*)(qsm + QKV_XS_B);     // [tok][d]
    __half* vts = (__half*)(qsm + QKV_VT_B);    // [e][tok]

    const int b   = blockIdx.y;
    const int n0  = blockIdx.x * 128;
    const int tid = threadIdx.x;

    // stage w packed: idx -> p = idx/4096, d = (idx>>5)&127, t = idx&31
#pragma unroll
    for (int i = 0; i < 24; i++) {
        const int idx = tid + i * 512;          // 0..12287
        const int p = idx >> 12;
        const int d = (idx >> 5) & 127;
        const int t = idx & 31;
        const float* wb = w + (p * DIN + d) * DOUT + t;
        wp2[idx] = pk2(wb[0], wb[32]);
    }
    // stage x tile [128][128]
    const float* xg = x + ((size_t)(b * SEQ + n0)) * DIN;
#pragma unroll
    for (int i = 0; i < 8; i++) {
        const int id4 = tid + i * 512;          // 4096 float4s
        const int tok = id4 >> 5, c4 = (id4 & 31) << 2;
        *(float4*)&xs[tok * XS_PAD + c4] = *(const float4*)&xg[tok * DIN + c4];
    }
    __syncthreads();

    const int tx = tid & 31;
    const int tok0 = (tid >> 5) * 8;

    u64 acc[8][3];
#pragma unroll
    for (int t = 0; t < 8; t++)
#pragma unroll
        for (int p = 0; p < 3; p++) acc[t][p] = 0ull;

#pragma unroll 2
    for (int d = 0; d < DIN; d++) {
        const u64 wq = wp2[(0 << 12) + (d << 5) + tx];   // LDS.64
        const u64 wk = wp2[(1 << 12) + (d << 5) + tx];
        const u64 wv = wp2[(2 << 12) + (d << 5) + tx];
#pragma unroll
        for (int t = 0; t < 8; t++) {
            const float xv = xs[(tok0 + t) * XS_PAD + d];   // broadcast LDS
            const u64 x2 = pk2(xv, xv);
            fma2(acc[t][0], x2, wq);
            fma2(acc[t][1], x2, wk);
            fma2(acc[t][2], x2, wv);
        }
    }

    // epilogue: Q/K hi+lo to gmem (coalesced), V staged to smem
#pragma unroll
    for (int t = 0; t < 8; t++) {
        const size_t row = (size_t)(b * SEQ + n0 + tok0 + t) * DOUT;
        float v0, v1;
        upk2(acc[t][0], v0, v1);
        v0 *= QSCALE; v1 *= QSCALE;
        __half h0 = __float2half_rn(v0), h1 = __float2half_rn(v1);
        g_qh[row + tx]      = h0; g_ql[row + tx]      = __float2half_rn(v0 - __half2float(h0));
        g_qh[row + tx + 32] = h1; g_ql[row + tx + 32] = __float2half_rn(v1 - __half2float(h1));
        upk2(acc[t][1], v0, v1);
        h0 = __float2half_rn(v0); h1 = __float2half_rn(v1);
        g_kh[row + tx]      = h0; g_kl[row + tx]      = __float2half_rn(v0 - __half2float(h0));
        g_kh[row + tx + 32] = h1; g_kl[row + tx + 32] = __float2half_rn(v1 - __half2float(h1));
        upk2(acc[t][2], v0, v1);
        vts[tx * VTS_PAD + tok0 + t]        = __float2half_rn(v0);
        vts[(tx + 32) * VTS_PAD + tok0 + t] = __float2half_rn(v1);
    }
    __syncthreads();

    // V^T coalesced: row e -> 16 consecutive tokens (32B) per thread
    const int e = tid >> 3, seg = tid & 7;
    const __half* srcv = vts + e * VTS_PAD + seg * 16;
    uint4* dstv = (uint4*)&g_vt[(((size_t)(b * DOUT + e)) << 12) + n0 + seg * 16];
    dstv[0] = *(const uint4*)(srcv);
    dstv[1] = *(const uint4*)(srcv + 8);
}

// ---------------------------------------------------------------------------
// Kernel 2: flash attention (unchanged from R8 best: 512 threads, split keys).
// ---------------------------------------------------------------------------
__device__ __forceinline__ void load_kv_h(uint32_t kb, int b, int kt, int htid) {
    const __half* kh = g_kh + ((size_t)(b * SEQ + kt)) * DOUT;
    const __half* kl = g_kl + ((size_t)(b * SEQ + kt)) * DOUT;
    const __half* vt = g_vt + (((size_t)b * DOUT) << 12) + kt;
#pragma unroll
    for (int i = 0; i < 2; i++) {
        const int id = htid + i * 256;
        const int row = id >> 3, c = id & 7;
        cp16(kb + KH_O + row * 144 + c * 16, kh + row * DOUT + c * 8);
        cp16(kb + KL_O + row * 144 + c * 16, kl + row * DOUT + c * 8);
        cp16(kb + VT_O + row * 144 + c * 16, vt + ((size_t)row << 12) + c * 8);
    }
}

__global__ __launch_bounds__(512, 1)
void attn_kernel(float* __restrict__ out) {
    extern __shared__ __align__(128) char sm[];
    const uint32_t smb = smem_u32(sm);
    const int tid  = threadIdx.x;
    const int wid  = tid >> 5;
    const int lane = tid & 31;
    const int g    = lane >> 2;
    const int tq   = lane & 3;
    const int half = wid & 1;
    const int pair = wid >> 1;
    const int htid = pair * 32 + lane;
    const int b    = blockIdx.y;
    const int q0   = blockIdx.x * BQ;
    const int r0   = pair * 16;
    const int k0   = half * 2048;

    const int lt = lane >> 3, lr = lane & 7;
    const uint32_t aoff = (uint32_t)((r0 + ((lt & 1) << 3) + lr) * 144 + ((lt >> 1) << 4));
    const uint32_t boff = (uint32_t)((((lane >> 4) << 3) + lr) * 144 + ((lt & 1) << 4));

    {
        const __half* qh = g_qh + ((size_t)(b * SEQ + q0)) * DOUT;
        const __half* ql = g_ql + ((size_t)(b * SEQ + q0)) * DOUT;
#pragma unroll
        for (int i = 0; i < 2; i++) {
            const int id = tid + i * 512;
            const int row = id >> 3, c = id & 7;
            cp16(smb + QH_B + row * 144 + c * 16, qh + row * DOUT + c * 8);
            cp16(smb + QL_B + row * 144 + c * 16, ql + row * DOUT + c * 8);
        }
        CP_COMMIT();
        load_kv_h(smb + KV_B(half, 0), b, k0, htid);
        CP_COMMIT();
        load_kv_h(smb + KV_B(half, 1), b, k0 + BK, htid);
        CP_COMMIT();
    }
    CP_WAIT2();
    __syncthreads();

    float o[8][4];
#pragma unroll
    for (int j = 0; j < 8; j++)
#pragma unroll
        for (int k = 0; k < 4; k++) o[j][k] = 0.f;
    float m0 = -3.0e38f, m1 = -3.0e38f, l0 = 0.f, l1 = 0.f;

    for (int t = 0; t < NTILES; t++) {
        CP_WAIT1();
        BARG(1 + half);
        if (t + 2 < NTILES)
            load_kv_h(smb + KV_B(half, (t + 2) % 3), b, k0 + (t + 2) * BK, htid);
        CP_COMMIT();

        const uint32_t kvb = smb + KV_B(half, t % 3);
        const uint32_t khb = kvb + KH_O + boff;
        const uint32_t klb = kvb + KL_O + boff;
        const uint32_t vtb = kvb + VT_O + boff;

        float s[8][4];
#pragma unroll
        for (int j = 0; j < 8; j++)
#pragma unroll
            for (int k = 0; k < 4; k++) s[j][k] = 0.f;

#pragma unroll
        for (int ks = 0; ks < 4; ks++) {
            uint32_t ah0, ah1, ah2, ah3, al0, al1, al2, al3;
            LDMX4(ah0, ah1, ah2, ah3, smb + QH_B + aoff + ks * 32);
            LDMX4(al0, al1, al2, al3, smb + QL_B + aoff + ks * 32);
#pragma unroll
            for (int jp = 0; jp < 4; jp++) {
                uint32_t bh0, bh1, bh2, bh3, bl0, bl1, bl2, bl3;
                LDMX4(bh0, bh1, bh2, bh3, khb + jp * 2304 + ks * 32);
                LDMX4(bl0, bl1, bl2, bl3, klb + jp * 2304 + ks * 32);
                MMA16816(s[2*jp],   ah0, ah1, ah2, ah3, bh0, bh1);
                MMA16816(s[2*jp+1], ah0, ah1, ah2, ah3, bh2, bh3);
                MMA16816(s[2*jp],   ah0, ah1, ah2, ah3, bl0, bl1);
                MMA16816(s[2*jp+1], ah0, ah1, ah2, ah3, bl2, bl3);
                MMA16816(s[2*jp],   al0, al1, al2, al3, bh0, bh1);
                MMA16816(s[2*jp+1], al0, al1, al2, al3, bh2, bh3);
            }
        }

        float mx0 = -3.0e38f, mx1 = -3.0e38f;
#pragma unroll
        for (int j = 0; j < 8; j++) {
            mx0 = fmaxf(mx0, fmaxf(s[j][0], s[j][1]));
            mx1 = fmaxf(mx1, fmaxf(s[j][2], s[j][3]));
        }
        mx0 = fmaxf(mx0, __shfl_xor_sync(0xffffffffu, mx0, 1));
        mx0 = fmaxf(mx0, __shfl_xor_sync(0xffffffffu, mx0, 2));
        mx1 = fmaxf(mx1, __shfl_xor_sync(0xffffffffu, mx1, 1));
        mx1 = fmaxf(mx1, __shfl_xor_sync(0xffffffffu, mx1, 2));
        const float mn0 = fmaxf(m0, mx0), mn1 = fmaxf(m1, mx1);
        const float c0 = ex2f(m0 - mn0), c1 = ex2f(m1 - mn1);

        uint32_t pa[4][4];
        float rs0 = 0.f, rs1 = 0.f;
#pragma unroll
        for (int j = 0; j < 8; j++) {
            const float e0 = ex2f(s[j][0] - mn0), e1 = ex2f(s[j][1] - mn0);
            const float e2 = ex2f(s[j][2] - mn1), e3 = ex2f(s[j][3] - mn1);
            rs0 += e0 + e1;  rs1 += e2 + e3;
            const __half2 h01 = __floats2half2_rn(e0, e1);
            const __half2 h23 = __floats2half2_rn(e2, e3);
            pa[j >> 1][(j & 1) * 2 + 0] = *(const uint32_t*)&h01;
            pa[j >> 1][(j & 1) * 2 + 1] = *(const uint32_t*)&h23;
        }
        rs0 += __shfl_xor_sync(0xffffffffu, rs0, 1);
        rs0 += __shfl_xor_sync(0xffffffffu, rs0, 2);
        rs1 += __shfl_xor_sync(0xffffffffu, rs1, 1);
        rs1 += __shfl_xor_sync(0xffffffffu, rs1, 2);
        l0 = l0 * c0 + rs0;  m0 = mn0;
        l1 = l1 * c1 + rs1;  m1 = mn1;

#pragma unroll
        for (int j = 0; j < 8; j++) {
            o[j][0] *= c0; o[j][1] *= c0;
            o[j][2] *= c1; o[j][3] *= c1;
        }
#pragma unroll
        for (int ks = 0; ks < 4; ks++) {
#pragma unroll
            for (int jp = 0; jp < 4; jp++) {
                uint32_t v0, v1, v2, v3;
                LDMX4(v0, v1, v2, v3, vtb + jp * 2304 + ks * 32);
                MMA16816(o[2*jp],   pa[ks][0], pa[ks][1], pa[ks][2], pa[ks][3], v0, v1);
                MMA16816(o[2*jp+1], pa[ks][0], pa[ks][1], pa[ks][2], pa[ks][3], v2, v3);
            }
        }
    }

    // ---- split-softmax merge ----
    __syncthreads();
    float* xo = (float*)sm;
    float* xm = (float*)(sm + 8 * 16 * 68 * 4);

    if (half == 1) {
#pragma unroll
        for (int j = 0; j < 8; j++) {
            const int col = j * 8 + 2 * tq;
            *(float2*)&xo[(r0 + g) * 68 + col]     = make_float2(o[j][0], o[j][1]);
            *(float2*)&xo[(r0 + g + 8) * 68 + col] = make_float2(o[j][2], o[j][3]);
        }
        if (tq == 0) {
            xm[(r0 + g) * 2]         = m0;  xm[(r0 + g) * 2 + 1]     = l0;
            xm[(r0 + g + 8) * 2]     = m1;  xm[(r0 + g + 8) * 2 + 1] = l1;
        }
    }
    __syncthreads();

    if (half == 0) {
        const float mo0 = xm[(r0 + g) * 2],     lo0 = xm[(r0 + g) * 2 + 1];
        const float mo1 = xm[(r0 + g + 8) * 2], lo1 = xm[(r0 + g + 8) * 2 + 1];
        const float mm0 = fmaxf(m0, mo0), mm1 = fmaxf(m1, mo1);
        const float ce0 = ex2f(m0 - mm0), co0 = ex2f(mo0 - mm0);
        const float ce1 = ex2f(m1 - mm1), co1 = ex2f(mo1 - mm1);
        const float rl0 = __frcp_rn(l0 * ce0 + lo0 * co0);
        const float rl1 = __frcp_rn(l1 * ce1 + lo1 * co1);

        float* O = out + ((size_t)(b * SEQ + q0 + r0 + g)) * DOUT;
#pragma unroll
        for (int j = 0; j < 8; j++) {
            const int col = j * 8 + 2 * tq;
            const float2 q0v = *(const float2*)&xo[(r0 + g) * 68 + col];
            const float2 q1v = *(const float2*)&xo[(r0 + g + 8) * 68 + col];
            *(float2*)&O[col] = make_float2(
                (o[j][0] * ce0 + q0v.x * co0) * rl0,
                (o[j][1] * ce0 + q0v.y * co0) * rl0);
            *(float2*)&O[8 * DOUT + col] = make_float2(
                (o[j][2] * ce1 + q1v.x * co1) * rl1,
                (o[j][3] * ce1 + q1v.y * co1) * rl1);
        }
    }
}

// ---------------------------------------------------------------------------
extern "C" void kernel_launch(void* const* d_in, const int* in_sizes, int n_in,
                              void* d_out, int out_size) {
    const float* x = (const float*)d_in[0];   // [4,4096,128]
    const float* w = (const float*)d_in[1];   // [3,128,64]
    float* out = (float*)d_out;               // [4,4096,64]

    cudaFuncSetAttribute(attn_kernel,
                         cudaFuncAttributeMaxDynamicSharedMemorySize, SMEM_BYTES);
    cudaFuncSetAttribute(qkv_proj_kernel,
                         cudaFuncAttributeMaxDynamicSharedMemorySize, QKV_SMEM);

    qkv_proj_kernel<<<dim3(SEQ / 128, BATCH), 512, QKV_SMEM>>>(x, w);
    attn_kernel<<<dim3(SEQ / BQ, BATCH), 512, SMEM_BYTES>>>(out);
}

// round 12
// speedup vs baseline: 1.3236x; 1.0158x over previous
#include <cuda_runtime.h>
#include <cuda_fp16.h>
#include <cstdint>

#define BATCH 4
#define SEQ   4096
#define DIN   128
#define DOUT  64
#define BQ    128
#define BK    64
#define NTILES 32          // per key-half: 2048/64

// Q pre-scale: 1/sqrt(64) * log2(e)  (softmax runs in exp2 domain)
#define QSCALE 0.1803368801111244f

// ---- fp16 scratch — device globals, no allocation ----
__device__ __half g_qh[BATCH * SEQ * DOUT];
__device__ __half g_ql[BATCH * SEQ * DOUT];
__device__ __half g_kh[BATCH * SEQ * DOUT];
__device__ __half g_kl[BATCH * SEQ * DOUT];
__device__ __half g_vt[BATCH * DOUT * SEQ];   // transposed: [b][dout][seq]

// ---- attn smem ----
#define QH_B       0
#define QL_B       18432
#define KV_B(h, s) (36864 + (h) * 82944 + (s) * 27648)
#define KH_O       0
#define KL_O       9216
#define VT_O       18432
#define SMEM_BYTES 202752

typedef unsigned long long u64;

__device__ __forceinline__ uint32_t smem_u32(const void* p) {
    uint32_t a;
    asm("{ .reg .u64 t; cvta.to.shared.u64 t, %1; cvt.u32.u64 %0, t; }" : "=r"(a) : "l"(p));
    return a;
}
__device__ __forceinline__ void cp16(uint32_t dst, const void* src) {
    asm volatile("cp.async.cg.shared.global [%0], [%1], 16;" :: "r"(dst), "l"(src));
}
#define CP_COMMIT() asm volatile("cp.async.commit_group;" ::: "memory")
#define CP_WAIT1()  asm volatile("cp.async.wait_group 1;" ::: "memory")
#define CP_WAIT2()  asm volatile("cp.async.wait_group 2;" ::: "memory")
#define BARG(id)    asm volatile("bar.sync %0, 256;" :: "r"(id) : "memory")

__device__ __forceinline__ float ex2f(float x) {
    float r; asm("ex2.approx.ftz.f32 %0, %1;" : "=f"(r) : "f"(x)); return r;
}

#define MMA16816(c, a0, a1, a2, a3, b0, b1) \
    asm volatile("mma.sync.aligned.m16n8k16.row.col.f32.f16.f16.f32 " \
                 "{%0,%1,%2,%3}, {%4,%5,%6,%7}, {%8,%9}, {%0,%1,%2,%3};" \
                 : "+f"((c)[0]), "+f"((c)[1]), "+f"((c)[2]), "+f"((c)[3]) \
                 : "r"(a0), "r"(a1), "r"(a2), "r"(a3), "r"(b0), "r"(b1))

#define LDMX4(r0, r1, r2, r3, a) \
    asm volatile("ldmatrix.sync.aligned.m8n8.x4.shared.b16 {%0,%1,%2,%3}, [%4];" \
                 : "=r"(r0), "=r"(r1), "=r"(r2), "=r"(r3) : "r"(a))

// ---- packed f32x2 ----
__device__ __forceinline__ u64 pk2(float lo, float hi) {
    u64 r; asm("mov.b64 %0, {%1, %2};" : "=l"(r) : "f"(lo), "f"(hi)); return r;
}
__device__ __forceinline__ void fma2(u64& d, u64 a, u64 b) {
    asm("fma.rn.f32x2 %0, %1, %2, %0;" : "+l"(d) : "l"(a), "l"(b));
}
__device__ __forceinline__ void upk2(u64 v, float& lo, float& hi) {
    asm("mov.b64 {%0, %1}, %2;" : "=f"(lo), "=f"(hi) : "l"(v));
}

// ---------------------------------------------------------------------------
// Kernel 1: QKV projection. 512 threads, 8 tokens/thread, w staged packed.
// Q and K stored as fp16 hi+lo splits (3-pass QK).
// ---------------------------------------------------------------------------
#define XS_PAD   132
#define VTS_PAD  136
#define QKV_W_B  0                       // [3][128][32] u64 = 98304
#define QKV_XS_B 98304                   // 128*132*4 = 67584
#define QKV_VT_B 165888                  // 64*136*2  = 17408
#define QKV_SMEM 183296

__global__ __launch_bounds__(512)
void qkv_proj_kernel(const float* __restrict__ x,
                     const float* __restrict__ w) {
    extern __shared__ __align__(16) char qsm[];
    u64*    wp2 = (u64*)(qsm + QKV_W_B);
    float*  xs  = (float*)(qsm + QKV_XS_B);
    __half* vts = (__half*)(qsm + QKV_VT_B);

    const int b   = blockIdx.y;
    const int n0  = blockIdx.x * 128;
    const int tid = threadIdx.x;

#pragma unroll
    for (int i = 0; i < 24; i++) {
        const int idx = tid + i * 512;
        const int p = idx >> 12;
        const int d = (idx >> 5) & 127;
        const int t = idx & 31;
        const float* wb = w + (p * DIN + d) * DOUT + t;
        wp2[idx] = pk2(wb[0], wb[32]);
    }
    const float* xg = x + ((size_t)(b * SEQ + n0)) * DIN;
#pragma unroll
    for (int i = 0; i < 8; i++) {
        const int id4 = tid + i * 512;
        const int tok = id4 >> 5, c4 = (id4 & 31) << 2;
        *(float4*)&xs[tok * XS_PAD + c4] = *(const float4*)&xg[tok * DIN + c4];
    }
    __syncthreads();

    const int tx = tid & 31;
    const int tok0 = (tid >> 5) * 8;

    u64 acc[8][3];
#pragma unroll
    for (int t = 0; t < 8; t++)
#pragma unroll
        for (int p = 0; p < 3; p++) acc[t][p] = 0ull;

#pragma unroll 2
    for (int d = 0; d < DIN; d++) {
        const u64 wq = wp2[(0 << 12) + (d << 5) + tx];
        const u64 wk = wp2[(1 << 12) + (d << 5) + tx];
        const u64 wv = wp2[(2 << 12) + (d << 5) + tx];
#pragma unroll
        for (int t = 0; t < 8; t++) {
            const float xv = xs[(tok0 + t) * XS_PAD + d];
            const u64 x2 = pk2(xv, xv);
            fma2(acc[t][0], x2, wq);
            fma2(acc[t][1], x2, wk);
            fma2(acc[t][2], x2, wv);
        }
    }

#pragma unroll
    for (int t = 0; t < 8; t++) {
        const size_t row = (size_t)(b * SEQ + n0 + tok0 + t) * DOUT;
        float v0, v1;
        upk2(acc[t][0], v0, v1);
        v0 *= QSCALE; v1 *= QSCALE;
        __half h0 = __float2half_rn(v0), h1 = __float2half_rn(v1);
        g_qh[row + tx]      = h0; g_ql[row + tx]      = __float2half_rn(v0 - __half2float(h0));
        g_qh[row + tx + 32] = h1; g_ql[row + tx + 32] = __float2half_rn(v1 - __half2float(h1));
        upk2(acc[t][1], v0, v1);
        h0 = __float2half_rn(v0); h1 = __float2half_rn(v1);
        g_kh[row + tx]      = h0; g_kl[row + tx]      = __float2half_rn(v0 - __half2float(h0));
        g_kh[row + tx + 32] = h1; g_kl[row + tx + 32] = __float2half_rn(v1 - __half2float(h1));
        upk2(acc[t][2], v0, v1);
        vts[tx * VTS_PAD + tok0 + t]        = __float2half_rn(v0);
        vts[(tx + 32) * VTS_PAD + tok0 + t] = __float2half_rn(v1);
    }
    __syncthreads();

    const int e = tid >> 3, seg = tid & 7;
    const __half* srcv = vts + e * VTS_PAD + seg * 16;
    uint4* dstv = (uint4*)&g_vt[(((size_t)(b * DOUT + e)) << 12) + n0 + seg * 16];
    dstv[0] = *(const uint4*)(srcv);
    dstv[1] = *(const uint4*)(srcv + 8);
}

// ---------------------------------------------------------------------------
// Kernel 2: flash attention, 512 threads, split keys, 3-pass QK.
// l maintained as an MMA ones-column (no per-tile sum reduction).
// ---------------------------------------------------------------------------
__device__ __forceinline__ void load_kv_h(uint32_t kb, int b, int kt, int htid) {
    const __half* kh = g_kh + ((size_t)(b * SEQ + kt)) * DOUT;
    const __half* kl = g_kl + ((size_t)(b * SEQ + kt)) * DOUT;
    const __half* vt = g_vt + (((size_t)b * DOUT) << 12) + kt;
#pragma unroll
    for (int i = 0; i < 2; i++) {
        const int id = htid + i * 256;
        const int row = id >> 3, c = id & 7;
        cp16(kb + KH_O + row * 144 + c * 16, kh + row * DOUT + c * 8);
        cp16(kb + KL_O + row * 144 + c * 16, kl + row * DOUT + c * 8);
        cp16(kb + VT_O + row * 144 + c * 16, vt + ((size_t)row << 12) + c * 8);
    }
}

__global__ __launch_bounds__(512, 1)
void attn_kernel(float* __restrict__ out) {
    extern __shared__ __align__(128) char sm[];
    const uint32_t smb = smem_u32(sm);
    const int tid  = threadIdx.x;
    const int wid  = tid >> 5;
    const int lane = tid & 31;
    const int g    = lane >> 2;
    const int tq   = lane & 3;
    const int half = wid & 1;
    const int pair = wid >> 1;
    const int htid = pair * 32 + lane;
    const int b    = blockIdx.y;
    const int q0   = blockIdx.x * BQ;
    const int r0   = pair * 16;
    const int k0   = half * 2048;

    const int lt = lane >> 3, lr = lane & 7;
    const uint32_t aoff = (uint32_t)((r0 + ((lt & 1) << 3) + lr) * 144 + ((lt >> 1) << 4));
    const uint32_t boff = (uint32_t)((((lane >> 4) << 3) + lr) * 144 + ((lt & 1) << 4));

    // constant B-fragment of the ones matrix (n-row 0 = 1.0, rows 1-7 = 0):
    // element B[k][n] depends only on n = g -> half2(1,1) iff g == 0.
    const uint32_t bON = (g == 0) ? 0x3C003C00u : 0u;

    {
        const __half* qh = g_qh + ((size_t)(b * SEQ + q0)) * DOUT;
        const __half* ql = g_ql + ((size_t)(b * SEQ + q0)) * DOUT;
#pragma unroll
        for (int i = 0; i < 2; i++) {
            const int id = tid + i * 512;
            const int row = id >> 3, c = id & 7;
            cp16(smb + QH_B + row * 144 + c * 16, qh + row * DOUT + c * 8);
            cp16(smb + QL_B + row * 144 + c * 16, ql + row * DOUT + c * 8);
        }
        CP_COMMIT();
        load_kv_h(smb + KV_B(half, 0), b, k0, htid);
        CP_COMMIT();
        load_kv_h(smb + KV_B(half, 1), b, k0 + BK, htid);
        CP_COMMIT();
    }
    CP_WAIT2();
    __syncthreads();

    float o[8][4], oL[4];
#pragma unroll
    for (int j = 0; j < 8; j++)
#pragma unroll
        for (int k = 0; k < 4; k++) o[j][k] = 0.f;
#pragma unroll
    for (int k = 0; k < 4; k++) oL[k] = 0.f;
    float m0 = -3.0e38f, m1 = -3.0e38f;

    for (int t = 0; t < NTILES; t++) {
        CP_WAIT1();
        BARG(1 + half);
        if (t + 2 < NTILES)
            load_kv_h(smb + KV_B(half, (t + 2) % 3), b, k0 + (t + 2) * BK, htid);
        CP_COMMIT();

        const uint32_t kvb = smb + KV_B(half, t % 3);
        const uint32_t khb = kvb + KH_O + boff;
        const uint32_t klb = kvb + KL_O + boff;
        const uint32_t vtb = kvb + VT_O + boff;

        // ---- QK^T: 16 x 64, 3-pass split-fp16 ----
        float s[8][4];
#pragma unroll
        for (int j = 0; j < 8; j++)
#pragma unroll
            for (int k = 0; k < 4; k++) s[j][k] = 0.f;

#pragma unroll
        for (int ks = 0; ks < 4; ks++) {
            uint32_t ah0, ah1, ah2, ah3, al0, al1, al2, al3;
            LDMX4(ah0, ah1, ah2, ah3, smb + QH_B + aoff + ks * 32);
            LDMX4(al0, al1, al2, al3, smb + QL_B + aoff + ks * 32);
#pragma unroll
            for (int jp = 0; jp < 4; jp++) {
                uint32_t bh0, bh1, bh2, bh3, bl0, bl1, bl2, bl3;
                LDMX4(bh0, bh1, bh2, bh3, khb + jp * 2304 + ks * 32);
                LDMX4(bl0, bl1, bl2, bl3, klb + jp * 2304 + ks * 32);
                MMA16816(s[2*jp],   ah0, ah1, ah2, ah3, bh0, bh1);
                MMA16816(s[2*jp+1], ah0, ah1, ah2, ah3, bh2, bh3);
                MMA16816(s[2*jp],   ah0, ah1, ah2, ah3, bl0, bl1);
                MMA16816(s[2*jp+1], ah0, ah1, ah2, ah3, bl2, bl3);
                MMA16816(s[2*jp],   al0, al1, al2, al3, bh0, bh1);
                MMA16816(s[2*jp+1], al0, al1, al2, al3, bh2, bh3);
            }
        }

        // ---- online softmax (exp2 domain); l handled by ones-column MMA ----
        float mx0 = -3.0e38f, mx1 = -3.0e38f;
#pragma unroll
        for (int j = 0; j < 8; j++) {
            mx0 = fmaxf(mx0, fmaxf(s[j][0], s[j][1]));
            mx1 = fmaxf(mx1, fmaxf(s[j][2], s[j][3]));
        }
        mx0 = fmaxf(mx0, __shfl_xor_sync(0xffffffffu, mx0, 1));
        mx0 = fmaxf(mx0, __shfl_xor_sync(0xffffffffu, mx0, 2));
        mx1 = fmaxf(mx1, __shfl_xor_sync(0xffffffffu, mx1, 1));
        mx1 = fmaxf(mx1, __shfl_xor_sync(0xffffffffu, mx1, 2));
        const float mn0 = fmaxf(m0, mx0), mn1 = fmaxf(m1, mx1);

        // rescale only if some row's max moved (warp-uniform branch)
        const bool upd = __any_sync(0xffffffffu, (mx0 > m0) | (mx1 > m1));
        if (upd) {
            const float c0 = ex2f(m0 - mn0), c1 = ex2f(m1 - mn1);
#pragma unroll
            for (int j = 0; j < 8; j++) {
                o[j][0] *= c0; o[j][1] *= c0;
                o[j][2] *= c1; o[j][3] *= c1;
            }
            oL[0] *= c0; oL[1] *= c0;
            oL[2] *= c1; oL[3] *= c1;
            m0 = mn0; m1 = mn1;
        }

        uint32_t pa[4][4];
#pragma unroll
        for (int j = 0; j < 8; j++) {
            const float e0 = ex2f(s[j][0] - m0), e1 = ex2f(s[j][1] - m0);
            const float e2 = ex2f(s[j][2] - m1), e3 = ex2f(s[j][3] - m1);
            const __half2 h01 = __floats2half2_rn(e0, e1);
            const __half2 h23 = __floats2half2_rn(e2, e3);
            pa[j >> 1][(j & 1) * 2 + 0] = *(const uint32_t*)&h01;
            pa[j >> 1][(j & 1) * 2 + 1] = *(const uint32_t*)&h23;
        }

        // ---- PV + l column ----
#pragma unroll
        for (int ks = 0; ks < 4; ks++) {
#pragma unroll
            for (int jp = 0; jp < 4; jp++) {
                uint32_t v0, v1, v2, v3;
                LDMX4(v0, v1, v2, v3, vtb + jp * 2304 + ks * 32);
                MMA16816(o[2*jp],   pa[ks][0], pa[ks][1], pa[ks][2], pa[ks][3], v0, v1);
                MMA16816(o[2*jp+1], pa[ks][0], pa[ks][1], pa[ks][2], pa[ks][3], v2, v3);
            }
            MMA16816(oL, pa[ks][0], pa[ks][1], pa[ks][2], pa[ks][3], bON, bON);
        }
    }

    // extract l (lives in col 0 -> tq == 0 lanes) and broadcast to quad
    const int qlead = lane & ~3;
    const float l0 = __shfl_sync(0xffffffffu, oL[0], qlead);
    const float l1 = __shfl_sync(0xffffffffu, oL[2], qlead);

    // ---- split-softmax merge ----
    __syncthreads();
    float* xo = (float*)sm;
    float* xm = (float*)(sm + 8 * 16 * 68 * 4);

    if (half == 1) {
#pragma unroll
        for (int j = 0; j < 8; j++) {
            const int col = j * 8 + 2 * tq;
            *(float2*)&xo[(r0 + g) * 68 + col]     = make_float2(o[j][0], o[j][1]);
            *(float2*)&xo[(r0 + g + 8) * 68 + col] = make_float2(o[j][2], o[j][3]);
        }
        if (tq == 0) {
            xm[(r0 + g) * 2]         = m0;  xm[(r0 + g) * 2 + 1]     = l0;
            xm[(r0 + g + 8) * 2]     = m1;  xm[(r0 + g + 8) * 2 + 1] = l1;
        }
    }
    __syncthreads();

    if (half == 0) {
        const float mo0 = xm[(r0 + g) * 2],     lo0 = xm[(r0 + g) * 2 + 1];
        const float mo1 = xm[(r0 + g + 8) * 2], lo1 = xm[(r0 + g + 8) * 2 + 1];
        const float mm0 = fmaxf(m0, mo0), mm1 = fmaxf(m1, mo1);
        const float ce0 = ex2f(m0 - mm0), co0 = ex2f(mo0 - mm0);
        const float ce1 = ex2f(m1 - mm1), co1 = ex2f(mo1 - mm1);
        const float rl0 = __frcp_rn(l0 * ce0 + lo0 * co0);
        const float rl1 = __frcp_rn(l1 * ce1 + lo1 * co1);

        float* O = out + ((size_t)(b * SEQ + q0 + r0 + g)) * DOUT;
#pragma unroll
        for (int j = 0; j < 8; j++) {
            const int col = j * 8 + 2 * tq;
            const float2 q0v = *(const float2*)&xo[(r0 + g) * 68 + col];
            const float2 q1v = *(const float2*)&xo[(r0 + g + 8) * 68 + col];
            *(float2*)&O[col] = make_float2(
                (o[j][0] * ce0 + q0v.x * co0) * rl0,
                (o[j][1] * ce0 + q0v.y * co0) * rl0);
            *(float2*)&O[8 * DOUT + col] = make_float2(
                (o[j][2] * ce1 + q1v.x * co1) * rl1,
                (o[j][3] * ce1 + q1v.y * co1) * rl1);
        }
    }
}

// ---------------------------------------------------------------------------
extern "C" void kernel_launch(void* const* d_in, const int* in_sizes, int n_in,
                              void* d_out, int out_size) {
    const float* x = (const float*)d_in[0];   // [4,4096,128]
    const float* w = (const float*)d_in[1];   // [3,128,64]
    float* out = (float*)d_out;               // [4,4096,64]

    cudaFuncSetAttribute(attn_kernel,
                         cudaFuncAttributeMaxDynamicSharedMemorySize, SMEM_BYTES);
    cudaFuncSetAttribute(qkv_proj_kernel,
                         cudaFuncAttributeMaxDynamicSharedMemorySize, QKV_SMEM);

    qkv_proj_kernel<<<dim3(SEQ / 128, BATCH), 512, QKV_SMEM>>>(x, w);
    attn_kernel<<<dim3(SEQ / BQ, BATCH), 512, SMEM_BYTES>>>(out);
}

// round 13
// speedup vs baseline: 1.3300x; 1.0048x over previous
#include <cuda_runtime.h>
#include <cuda_fp16.h>
#include <cstdint>

#define BATCH 4
#define SEQ   4096
#define DIN   128
#define DOUT  64
#define BQ    128
#define BK    64
#define NTILES 32          // per key-half: 2048/64

// Q pre-scale: 1/sqrt(64) * log2(e)  (softmax runs in exp2 domain)
#define QSCALE 0.1803368801111244f

// ---- fp16 scratch — device globals, no allocation ----
__device__ __half g_qh[BATCH * SEQ * DOUT];
__device__ __half g_ql[BATCH * SEQ * DOUT];
__device__ __half g_kh[BATCH * SEQ * DOUT];
__device__ __half g_kl[BATCH * SEQ * DOUT];
__device__ __half g_vt[BATCH * DOUT * SEQ];   // transposed: [b][dout][seq]

// ---- attn smem ----
#define QH_B       0
#define QL_B       18432
#define KV_B(h, s) (36864 + (h) * 82944 + (s) * 27648)
#define KH_O       0
#define KL_O       9216
#define VT_O       18432
#define SMEM_BYTES 202752

typedef unsigned long long u64;

__device__ __forceinline__ uint32_t smem_u32(const void* p) {
    uint32_t a;
    asm("{ .reg .u64 t; cvta.to.shared.u64 t, %1; cvt.u32.u64 %0, t; }" : "=r"(a) : "l"(p));
    return a;
}
__device__ __forceinline__ void cp16(uint32_t dst, const void* src) {
    asm volatile("cp.async.cg.shared.global [%0], [%1], 16;" :: "r"(dst), "l"(src));
}
#define CP_COMMIT() asm volatile("cp.async.commit_group;" ::: "memory")
#define CP_WAIT1()  asm volatile("cp.async.wait_group 1;" ::: "memory")
#define CP_WAIT2()  asm volatile("cp.async.wait_group 2;" ::: "memory")
#define BARG(id)    asm volatile("bar.sync %0, 256;" :: "r"(id) : "memory")

__device__ __forceinline__ float ex2f(float x) {
    float r; asm("ex2.approx.ftz.f32 %0, %1;" : "=f"(r) : "f"(x)); return r;
}

#define MMA16816(c, a0, a1, a2, a3, b0, b1) \
    asm volatile("mma.sync.aligned.m16n8k16.row.col.f32.f16.f16.f32 " \
                 "{%0,%1,%2,%3}, {%4,%5,%6,%7}, {%8,%9}, {%0,%1,%2,%3};" \
                 : "+f"((c)[0]), "+f"((c)[1]), "+f"((c)[2]), "+f"((c)[3]) \
                 : "r"(a0), "r"(a1), "r"(a2), "r"(a3), "r"(b0), "r"(b1))

#define LDMX4(r0, r1, r2, r3, a) \
    asm volatile("ldmatrix.sync.aligned.m8n8.x4.shared.b16 {%0,%1,%2,%3}, [%4];" \
                 : "=r"(r0), "=r"(r1), "=r"(r2), "=r"(r3) : "r"(a))

// ---- packed f32x2 ----
__device__ __forceinline__ u64 pk2(float lo, float hi) {
    u64 r; asm("mov.b64 %0, {%1, %2};" : "=l"(r) : "f"(lo), "f"(hi)); return r;
}
__device__ __forceinline__ void fma2(u64& d, u64 a, u64 b) {
    asm("fma.rn.f32x2 %0, %1, %2, %0;" : "+l"(d) : "l"(a), "l"(b));
}
__device__ __forceinline__ void upk2(u64 v, float& lo, float& hi) {
    asm("mov.b64 {%0, %1}, %2;" : "=f"(lo), "=f"(hi) : "l"(v));
}

// ---------------------------------------------------------------------------
// Kernel 1: QKV projection. 512 threads, 8 tokens/thread, w staged packed.
// Q and K stored as fp16 hi+lo splits (3-pass QK).
// ---------------------------------------------------------------------------
#define XS_PAD   132
#define VTS_PAD  136
#define QKV_W_B  0                       // [3][128][32] u64 = 98304
#define QKV_XS_B 98304                   // 128*132*4 = 67584
#define QKV_VT_B 165888                  // 64*136*2  = 17408
#define QKV_SMEM 183296

__global__ __launch_bounds__(512)
void qkv_proj_kernel(const float* __restrict__ x,
                     const float* __restrict__ w) {
    extern __shared__ __align__(16) char qsm[];
    u64*    wp2 = (u64*)(qsm + QKV_W_B);
    float*  xs  = (float*)(qsm + QKV_XS_B);
    __half* vts = (__half*)(qsm + QKV_VT_B);

    const int b   = blockIdx.y;
    const int n0  = blockIdx.x * 128;
    const int tid = threadIdx.x;

#pragma unroll
    for (int i = 0; i < 24; i++) {
        const int idx = tid + i * 512;
        const int p = idx >> 12;
        const int d = (idx >> 5) & 127;
        const int t = idx & 31;
        const float* wb = w + (p * DIN + d) * DOUT + t;
        wp2[idx] = pk2(wb[0], wb[32]);
    }
    const float* xg = x + ((size_t)(b * SEQ + n0)) * DIN;
#pragma unroll
    for (int i = 0; i < 8; i++) {
        const int id4 = tid + i * 512;
        const int tok = id4 >> 5, c4 = (id4 & 31) << 2;
        *(float4*)&xs[tok * XS_PAD + c4] = *(const float4*)&xg[tok * DIN + c4];
    }
    __syncthreads();

    const int tx = tid & 31;
    const int tok0 = (tid >> 5) * 8;

    u64 acc[8][3];
#pragma unroll
    for (int t = 0; t < 8; t++)
#pragma unroll
        for (int p = 0; p < 3; p++) acc[t][p] = 0ull;

#pragma unroll 2
    for (int d = 0; d < DIN; d++) {
        const u64 wq = wp2[(0 << 12) + (d << 5) + tx];
        const u64 wk = wp2[(1 << 12) + (d << 5) + tx];
        const u64 wv = wp2[(2 << 12) + (d << 5) + tx];
#pragma unroll
        for (int t = 0; t < 8; t++) {
            const float xv = xs[(tok0 + t) * XS_PAD + d];
            const u64 x2 = pk2(xv, xv);
            fma2(acc[t][0], x2, wq);
            fma2(acc[t][1], x2, wk);
            fma2(acc[t][2], x2, wv);
        }
    }

#pragma unroll
    for (int t = 0; t < 8; t++) {
        const size_t row = (size_t)(b * SEQ + n0 + tok0 + t) * DOUT;
        float v0, v1;
        upk2(acc[t][0], v0, v1);
        v0 *= QSCALE; v1 *= QSCALE;
        __half h0 = __float2half_rn(v0), h1 = __float2half_rn(v1);
        g_qh[row + tx]      = h0; g_ql[row + tx]      = __float2half_rn(v0 - __half2float(h0));
        g_qh[row + tx + 32] = h1; g_ql[row + tx + 32] = __float2half_rn(v1 - __half2float(h1));
        upk2(acc[t][1], v0, v1);
        h0 = __float2half_rn(v0); h1 = __float2half_rn(v1);
        g_kh[row + tx]      = h0; g_kl[row + tx]      = __float2half_rn(v0 - __half2float(h0));
        g_kh[row + tx + 32] = h1; g_kl[row + tx + 32] = __float2half_rn(v1 - __half2float(h1));
        upk2(acc[t][2], v0, v1);
        vts[tx * VTS_PAD + tok0 + t]        = __float2half_rn(v0);
        vts[(tx + 32) * VTS_PAD + tok0 + t] = __float2half_rn(v1);
    }
    __syncthreads();

    const int e = tid >> 3, seg = tid & 7;
    const __half* srcv = vts + e * VTS_PAD + seg * 16;
    uint4* dstv = (uint4*)&g_vt[(((size_t)(b * DOUT + e)) << 12) + n0 + seg * 16];
    dstv[0] = *(const uint4*)(srcv);
    dstv[1] = *(const uint4*)(srcv + 8);
}

// ---------------------------------------------------------------------------
// Kernel 2: flash attention, 512 threads, split keys, 3-pass QK.
// Tiles whose weights all flush to fp16 zero skip softmax + PV entirely
// (bitwise-equivalent to computing them).
// ---------------------------------------------------------------------------
__device__ __forceinline__ void load_kv_h(uint32_t kb, int b, int kt, int htid) {
    const __half* kh = g_kh + ((size_t)(b * SEQ + kt)) * DOUT;
    const __half* kl = g_kl + ((size_t)(b * SEQ + kt)) * DOUT;
    const __half* vt = g_vt + (((size_t)b * DOUT) << 12) + kt;
#pragma unroll
    for (int i = 0; i < 2; i++) {
        const int id = htid + i * 256;
        const int row = id >> 3, c = id & 7;
        cp16(kb + KH_O + row * 144 + c * 16, kh + row * DOUT + c * 8);
        cp16(kb + KL_O + row * 144 + c * 16, kl + row * DOUT + c * 8);
        cp16(kb + VT_O + row * 144 + c * 16, vt + ((size_t)row << 12) + c * 8);
    }
}

__global__ __launch_bounds__(512, 1)
void attn_kernel(float* __restrict__ out) {
    extern __shared__ __align__(128) char sm[];
    const uint32_t smb = smem_u32(sm);
    const int tid  = threadIdx.x;
    const int wid  = tid >> 5;
    const int lane = tid & 31;
    const int g    = lane >> 2;
    const int tq   = lane & 3;
    const int half = wid & 1;
    const int pair = wid >> 1;
    const int htid = pair * 32 + lane;
    const int b    = blockIdx.y;
    const int q0   = blockIdx.x * BQ;
    const int r0   = pair * 16;
    const int k0   = half * 2048;

    const int lt = lane >> 3, lr = lane & 7;
    const uint32_t aoff = (uint32_t)((r0 + ((lt & 1) << 3) + lr) * 144 + ((lt >> 1) << 4));
    const uint32_t boff = (uint32_t)((((lane >> 4) << 3) + lr) * 144 + ((lt & 1) << 4));

    // constant B-fragment of the ones matrix (n-row 0 = 1.0, rows 1-7 = 0)
    const uint32_t bON = (g == 0) ? 0x3C003C00u : 0u;

    {
        const __half* qh = g_qh + ((size_t)(b * SEQ + q0)) * DOUT;
        const __half* ql = g_ql + ((size_t)(b * SEQ + q0)) * DOUT;
#pragma unroll
        for (int i = 0; i < 2; i++) {
            const int id = tid + i * 512;
            const int row = id >> 3, c = id & 7;
            cp16(smb + QH_B + row * 144 + c * 16, qh + row * DOUT + c * 8);
            cp16(smb + QL_B + row * 144 + c * 16, ql + row * DOUT + c * 8);
        }
        CP_COMMIT();
        load_kv_h(smb + KV_B(half, 0), b, k0, htid);
        CP_COMMIT();
        load_kv_h(smb + KV_B(half, 1), b, k0 + BK, htid);
        CP_COMMIT();
    }
    CP_WAIT2();
    __syncthreads();

    float o[8][4], oL[4];
#pragma unroll
    for (int j = 0; j < 8; j++)
#pragma unroll
        for (int k = 0; k < 4; k++) o[j][k] = 0.f;
#pragma unroll
    for (int k = 0; k < 4; k++) oL[k] = 0.f;
    float m0 = -3.0e38f, m1 = -3.0e38f;

    for (int t = 0; t < NTILES; t++) {
        CP_WAIT1();
        BARG(1 + half);
        if (t + 2 < NTILES)
            load_kv_h(smb + KV_B(half, (t + 2) % 3), b, k0 + (t + 2) * BK, htid);
        CP_COMMIT();

        const uint32_t kvb = smb + KV_B(half, t % 3);
        const uint32_t khb = kvb + KH_O + boff;
        const uint32_t klb = kvb + KL_O + boff;
        const uint32_t vtb = kvb + VT_O + boff;

        // ---- QK^T: 16 x 64, 3-pass split-fp16 ----
        float s[8][4];
#pragma unroll
        for (int j = 0; j < 8; j++)
#pragma unroll
            for (int k = 0; k < 4; k++) s[j][k] = 0.f;

#pragma unroll
        for (int ks = 0; ks < 4; ks++) {
            uint32_t ah0, ah1, ah2, ah3, al0, al1, al2, al3;
            LDMX4(ah0, ah1, ah2, ah3, smb + QH_B + aoff + ks * 32);
            LDMX4(al0, al1, al2, al3, smb + QL_B + aoff + ks * 32);
#pragma unroll
            for (int jp = 0; jp < 4; jp++) {
                uint32_t bh0, bh1, bh2, bh3, bl0, bl1, bl2, bl3;
                LDMX4(bh0, bh1, bh2, bh3, khb + jp * 2304 + ks * 32);
                LDMX4(bl0, bl1, bl2, bl3, klb + jp * 2304 + ks * 32);
                MMA16816(s[2*jp],   ah0, ah1, ah2, ah3, bh0, bh1);
                MMA16816(s[2*jp+1], ah0, ah1, ah2, ah3, bh2, bh3);
                MMA16816(s[2*jp],   ah0, ah1, ah2, ah3, bl0, bl1);
                MMA16816(s[2*jp+1], ah0, ah1, ah2, ah3, bl2, bl3);
                MMA16816(s[2*jp],   al0, al1, al2, al3, bh0, bh1);
                MMA16816(s[2*jp+1], al0, al1, al2, al3, bh2, bh3);
            }
        }

        // ---- row max for this tile ----
        float mx0 = -3.0e38f, mx1 = -3.0e38f;
#pragma unroll
        for (int j = 0; j < 8; j++) {
            mx0 = fmaxf(mx0, fmaxf(s[j][0], s[j][1]));
            mx1 = fmaxf(mx1, fmaxf(s[j][2], s[j][3]));
        }
        mx0 = fmaxf(mx0, __shfl_xor_sync(0xffffffffu, mx0, 1));
        mx0 = fmaxf(mx0, __shfl_xor_sync(0xffffffffu, mx0, 2));
        mx1 = fmaxf(mx1, __shfl_xor_sync(0xffffffffu, mx1, 1));
        mx1 = fmaxf(mx1, __shfl_xor_sync(0xffffffffu, mx1, 2));

        // ---- all-flush test: every weight would round to 0.0h ----
        const bool active = __any_sync(0xffffffffu,
                                       (mx0 > m0 - 25.f) | (mx1 > m1 - 25.f));
        if (!active) continue;

        const float mn0 = fmaxf(m0, mx0), mn1 = fmaxf(m1, mx1);
        const bool upd = __any_sync(0xffffffffu, (mx0 > m0) | (mx1 > m1));
        if (upd) {
            const float c0 = ex2f(m0 - mn0), c1 = ex2f(m1 - mn1);
#pragma unroll
            for (int j = 0; j < 8; j++) {
                o[j][0] *= c0; o[j][1] *= c0;
                o[j][2] *= c1; o[j][3] *= c1;
            }
            oL[0] *= c0; oL[1] *= c0;
            oL[2] *= c1; oL[3] *= c1;
            m0 = mn0; m1 = mn1;
        }

        uint32_t pa[4][4];
#pragma unroll
        for (int j = 0; j < 8; j++) {
            const float e0 = ex2f(s[j][0] - m0), e1 = ex2f(s[j][1] - m0);
            const float e2 = ex2f(s[j][2] - m1), e3 = ex2f(s[j][3] - m1);
            const __half2 h01 = __floats2half2_rn(e0, e1);
            const __half2 h23 = __floats2half2_rn(e2, e3);
            pa[j >> 1][(j & 1) * 2 + 0] = *(const uint32_t*)&h01;
            pa[j >> 1][(j & 1) * 2 + 1] = *(const uint32_t*)&h23;
        }

        // ---- PV + l column ----
#pragma unroll
        for (int ks = 0; ks < 4; ks++) {
#pragma unroll
            for (int jp = 0; jp < 4; jp++) {
                uint32_t v0, v1, v2, v3;
                LDMX4(v0, v1, v2, v3, vtb + jp * 2304 + ks * 32);
                MMA16816(o[2*jp],   pa[ks][0], pa[ks][1], pa[ks][2], pa[ks][3], v0, v1);
                MMA16816(o[2*jp+1], pa[ks][0], pa[ks][1], pa[ks][2], pa[ks][3], v2, v3);
            }
            MMA16816(oL, pa[ks][0], pa[ks][1], pa[ks][2], pa[ks][3], bON, bON);
        }
    }

    // extract l (col 0 -> tq == 0 lanes), broadcast to quad
    const int qlead = lane & ~3;
    const float l0 = __shfl_sync(0xffffffffu, oL[0], qlead);
    const float l1 = __shfl_sync(0xffffffffu, oL[2], qlead);

    // ---- split-softmax merge ----
    __syncthreads();
    float* xo = (float*)sm;
    float* xm = (float*)(sm + 8 * 16 * 68 * 4);

    if (half == 1) {
#pragma unroll
        for (int j = 0; j < 8; j++) {
            const int col = j * 8 + 2 * tq;
            *(float2*)&xo[(r0 + g) * 68 + col]     = make_float2(o[j][0], o[j][1]);
            *(float2*)&xo[(r0 + g + 8) * 68 + col] = make_float2(o[j][2], o[j][3]);
        }
        if (tq == 0) {
            xm[(r0 + g) * 2]         = m0;  xm[(r0 + g) * 2 + 1]     = l0;
            xm[(r0 + g + 8) * 2]     = m1;  xm[(r0 + g + 8) * 2 + 1] = l1;
        }
    }
    __syncthreads();

    if (half == 0) {
        const float mo0 = xm[(r0 + g) * 2],     lo0 = xm[(r0 + g) * 2 + 1];
        const float mo1 = xm[(r0 + g + 8) * 2], lo1 = xm[(r0 + g + 8) * 2 + 1];
        const float mm0 = fmaxf(m0, mo0), mm1 = fmaxf(m1, mo1);
        const float ce0 = ex2f(m0 - mm0), co0 = ex2f(mo0 - mm0);
        const float ce1 = ex2f(m1 - mm1), co1 = ex2f(mo1 - mm1);
        const float rl0 = __frcp_rn(l0 * ce0 + lo0 * co0);
        const float rl1 = __frcp_rn(l1 * ce1 + lo1 * co1);

        float* O = out + ((size_t)(b * SEQ + q0 + r0 + g)) * DOUT;
#pragma unroll
        for (int j = 0; j < 8; j++) {
            const int col = j * 8 + 2 * tq;
            const float2 q0v = *(const float2*)&xo[(r0 + g) * 68 + col];
            const float2 q1v = *(const float2*)&xo[(r0 + g + 8) * 68 + col];
            *(float2*)&O[col] = make_float2(
                (o[j][0] * ce0 + q0v.x * co0) * rl0,
                (o[j][1] * ce0 + q0v.y * co0) * rl0);
            *(float2*)&O[8 * DOUT + col] = make_float2(
                (o[j][2] * ce1 + q1v.x * co1) * rl1,
                (o[j][3] * ce1 + q1v.y * co1) * rl1);
        }
    }
}

// ---------------------------------------------------------------------------
extern "C" void kernel_launch(void* const* d_in, const int* in_sizes, int n_in,
                              void* d_out, int out_size) {
    const float* x = (const float*)d_in[0];   // [4,4096,128]
    const float* w = (const float*)d_in[1];   // [3,128,64]
    float* out = (float*)d_out;               // [4,4096,64]

    cudaFuncSetAttribute(attn_kernel,
                         cudaFuncAttributeMaxDynamicSharedMemorySize, SMEM_BYTES);
    cudaFuncSetAttribute(qkv_proj_kernel,
                         cudaFuncAttributeMaxDynamicSharedMemorySize, QKV_SMEM);

    qkv_proj_kernel<<<dim3(SEQ / 128, BATCH), 512, QKV_SMEM>>>(x, w);
    attn_kernel<<<dim3(SEQ / BQ, BATCH), 512, SMEM_BYTES>>>(out);
}

// round 14
// speedup vs baseline: 1.4498x; 1.0901x over previous
#include <cuda_runtime.h>
#include <cuda_fp16.h>
#include <cstdint>

#define BATCH 4
#define SEQ   4096
#define DIN   128
#define DOUT  64
#define BQ    128
#define BK    64
#define NTILES 32          // per key-half: 2048/64

// Q pre-scale: 1/sqrt(64) * log2(e)  (softmax runs in exp2 domain)
#define QSCALE 0.1803368801111244f

// ---- fp16 scratch — device globals, no allocation ----
__device__ __half g_qh[BATCH * SEQ * DOUT];
__device__ __half g_ql[BATCH * SEQ * DOUT];
__device__ __half g_kh[BATCH * SEQ * DOUT];
__device__ __half g_kl[BATCH * SEQ * DOUT];
__device__ __half g_vt[BATCH * DOUT * SEQ];   // transposed: [b][dout][seq]

// ---- attn smem ----
#define QH_B       0
#define QL_B       18432
#define KV_B(h, s) (36864 + (h) * 82944 + (s) * 27648)
#define KH_O       0
#define KL_O       9216
#define VT_O       18432
#define SMEM_BYTES 202752

typedef unsigned long long u64;

__device__ __forceinline__ uint32_t smem_u32(const void* p) {
    uint32_t a;
    asm("{ .reg .u64 t; cvta.to.shared.u64 t, %1; cvt.u32.u64 %0, t; }" : "=r"(a) : "l"(p));
    return a;
}
__device__ __forceinline__ void cp16(uint32_t dst, const void* src) {
    asm volatile("cp.async.cg.shared.global [%0], [%1], 16;" :: "r"(dst), "l"(src));
}
#define CP_COMMIT() asm volatile("cp.async.commit_group;" ::: "memory")
#define CP_WAIT1()  asm volatile("cp.async.wait_group 1;" ::: "memory")
#define CP_WAIT2()  asm volatile("cp.async.wait_group 2;" ::: "memory")
#define BARG(id)    asm volatile("bar.sync %0, 256;" :: "r"(id) : "memory")

__device__ __forceinline__ float ex2f(float x) {
    float r; asm("ex2.approx.ftz.f32 %0, %1;" : "=f"(r) : "f"(x)); return r;
}

#define MMA16816(c, a0, a1, a2, a3, b0, b1) \
    asm volatile("mma.sync.aligned.m16n8k16.row.col.f32.f16.f16.f32 " \
                 "{%0,%1,%2,%3}, {%4,%5,%6,%7}, {%8,%9}, {%0,%1,%2,%3};" \
                 : "+f"((c)[0]), "+f"((c)[1]), "+f"((c)[2]), "+f"((c)[3]) \
                 : "r"(a0), "r"(a1), "r"(a2), "r"(a3), "r"(b0), "r"(b1))

#define LDMX4(r0, r1, r2, r3, a) \
    asm volatile("ldmatrix.sync.aligned.m8n8.x4.shared.b16 {%0,%1,%2,%3}, [%4];" \
                 : "=r"(r0), "=r"(r1), "=r"(r2), "=r"(r3) : "r"(a))

// ---------------------------------------------------------------------------
// Kernel 1: QKV projection via tensor cores. 3-pass split-fp16 on w:
//   x@w ~= xh@wh + xh@wl + xl@wh   (dropped xl@wl ~ 2^-22 rel)
// Each CTA: 128 tokens x 192 output cols; 16 warps = 8 row-groups x 2 halves.
// ---------------------------------------------------------------------------
#define QP_STRIDE 272                    // row stride bytes (136 halves); %128=16
#define XH2_B   0                        // 128 * 272 = 34816
#define XL2_B   34816
#define WH2_B   69632                    // 192 * 272 = 52224
#define WL2_B   121856
#define VTS2_B  174080                   // 64 * 136 * 2 = 17408
#define VTS_PAD 136
#define QKV_SMEM 191488

__global__ __launch_bounds__(512)
void qkv_proj_kernel(const float* __restrict__ x,
                     const float* __restrict__ w) {
    extern __shared__ __align__(128) char qsm[];
    const uint32_t smb = smem_u32(qsm);
    __half* xh  = (__half*)(qsm + XH2_B);
    __half* xl  = (__half*)(qsm + XL2_B);
    __half* wh  = (__half*)(qsm + WH2_B);   // [pcol = p*64+e][d]
    __half* wl  = (__half*)(qsm + WL2_B);
    __half* vts = (__half*)(qsm + VTS2_B);  // [e][token]

    const int b   = blockIdx.y;
    const int n0  = blockIdx.x * 128;
    const int tid = threadIdx.x;

    // ---- stage w transposed + split (fold QSCALE into p==0) ----
#pragma unroll
    for (int i = 0; i < 48; i++) {
        const int idx = tid + i * 512;          // 0..24575
        const int p = idx >> 13;                // /8192
        const int rem = idx & 8191;
        const int d = rem >> 6, e = rem & 63;
        float v = w[idx];
        if (p == 0) v *= QSCALE;
        const __half h = __float2half_rn(v);
        const int row = p * 64 + e;
        wh[row * 136 + d] = h;
        wl[row * 136 + d] = __float2half_rn(v - __half2float(h));
    }
    // ---- stage x split ----
    const float* xg = x + ((size_t)(b * SEQ + n0)) * DIN;
#pragma unroll
    for (int i = 0; i < 32; i++) {
        const int idx = tid + i * 512;          // 0..16383
        const int tok = idx >> 7, d = idx & 127;
        const float v = xg[idx];
        const __half h = __float2half_rn(v);
        xh[tok * 136 + d] = h;
        xl[tok * 136 + d] = __float2half_rn(v - __half2float(h));
    }
    __syncthreads();

    const int wid  = tid >> 5;
    const int lane = tid & 31;
    const int g    = lane >> 2;
    const int tq   = lane & 3;
    const int pairw = wid >> 1;          // token group 0..7
    const int halfn = wid & 1;           // col half: 0 -> 0-95, 1 -> 96-191
    const int r0    = pairw * 16;

    const int lt = lane >> 3, lr = lane & 7;
    const uint32_t aoff = (uint32_t)((r0 + ((lt & 1) << 3) + lr) * QP_STRIDE + ((lt >> 1) << 4));
    const uint32_t boff = (uint32_t)((((lane >> 4) << 3) + lr) * QP_STRIDE + ((lt & 1) << 4));

    float acc[12][4];
#pragma unroll
    for (int j = 0; j < 12; j++)
#pragma unroll
        for (int k = 0; k < 4; k++) acc[j][k] = 0.f;

#pragma unroll
    for (int ks = 0; ks < 8; ks++) {
        uint32_t ah0, ah1, ah2, ah3, al0, al1, al2, al3;
        LDMX4(ah0, ah1, ah2, ah3, smb + XH2_B + aoff + ks * 32);
        LDMX4(al0, al1, al2, al3, smb + XL2_B + aoff + ks * 32);
#pragma unroll
        for (int jp = 0; jp < 6; jp++) {
            const uint32_t bb = (uint32_t)((halfn * 96 + jp * 16) * QP_STRIDE) + boff + ks * 32;
            uint32_t bh0, bh1, bh2, bh3, bl0, bl1, bl2, bl3;
            LDMX4(bh0, bh1, bh2, bh3, smb + WH2_B + bb);
            LDMX4(bl0, bl1, bl2, bl3, smb + WL2_B + bb);
            MMA16816(acc[2*jp],   ah0, ah1, ah2, ah3, bh0, bh1);
            MMA16816(acc[2*jp+1], ah0, ah1, ah2, ah3, bh2, bh3);
            MMA16816(acc[2*jp],   ah0, ah1, ah2, ah3, bl0, bl1);
            MMA16816(acc[2*jp+1], ah0, ah1, ah2, ah3, bl2, bl3);
            MMA16816(acc[2*jp],   al0, al1, al2, al3, bh0, bh1);
            MMA16816(acc[2*jp+1], al0, al1, al2, al3, bh2, bh3);
        }
    }

    // ---- epilogue: write Q/K hi+lo, stage V to smem ----
#pragma unroll
    for (int j = 0; j < 12; j++) {
        const int col = halfn * 96 + j * 8 + 2 * tq;   // nfrag never crosses p
        const int p = col >> 6, e = col & 63;
        const int rowA = r0 + g, rowB = r0 + g + 8;
#pragma unroll
        for (int h2 = 0; h2 < 2; h2++) {
            const int row = h2 ? rowB : rowA;
            const float v0 = acc[j][h2 * 2], v1 = acc[j][h2 * 2 + 1];
            if (p == 2) {
                vts[e * VTS_PAD + row]       = __float2half_rn(v0);
                vts[(e + 1) * VTS_PAD + row] = __float2half_rn(v1);
            } else {
                const __half h0 = __float2half_rn(v0), h1 = __float2half_rn(v1);
                const __half l0 = __float2half_rn(v0 - __half2float(h0));
                const __half l1 = __float2half_rn(v1 - __half2float(h1));
                const size_t go = (size_t)(b * SEQ + n0 + row) * DOUT + e;
                if (p == 0) {
                    *(__half2*)&g_qh[go] = __halves2half2(h0, h1);
                    *(__half2*)&g_ql[go] = __halves2half2(l0, l1);
                } else {
                    *(__half2*)&g_kh[go] = __halves2half2(h0, h1);
                    *(__half2*)&g_kl[go] = __halves2half2(l0, l1);
                }
            }
        }
    }
    __syncthreads();

    // V^T coalesced: row e -> 16 consecutive tokens per thread
    const int e = tid >> 3, seg = tid & 7;
    const __half* srcv = vts + e * VTS_PAD + seg * 16;
    uint4* dstv = (uint4*)&g_vt[(((size_t)(b * DOUT + e)) << 12) + n0 + seg * 16];
    dstv[0] = *(const uint4*)(srcv);
    dstv[1] = *(const uint4*)(srcv + 8);
}

// ---------------------------------------------------------------------------
// Kernel 2: flash attention (unchanged R12 best).
// ---------------------------------------------------------------------------
__device__ __forceinline__ void load_kv_h(uint32_t kb, int b, int kt, int htid) {
    const __half* kh = g_kh + ((size_t)(b * SEQ + kt)) * DOUT;
    const __half* kl = g_kl + ((size_t)(b * SEQ + kt)) * DOUT;
    const __half* vt = g_vt + (((size_t)b * DOUT) << 12) + kt;
#pragma unroll
    for (int i = 0; i < 2; i++) {
        const int id = htid + i * 256;
        const int row = id >> 3, c = id & 7;
        cp16(kb + KH_O + row * 144 + c * 16, kh + row * DOUT + c * 8);
        cp16(kb + KL_O + row * 144 + c * 16, kl + row * DOUT + c * 8);
        cp16(kb + VT_O + row * 144 + c * 16, vt + ((size_t)row << 12) + c * 8);
    }
}

__global__ __launch_bounds__(512, 1)
void attn_kernel(float* __restrict__ out) {
    extern __shared__ __align__(128) char sm[];
    const uint32_t smb = smem_u32(sm);
    const int tid  = threadIdx.x;
    const int wid  = tid >> 5;
    const int lane = tid & 31;
    const int g    = lane >> 2;
    const int tq   = lane & 3;
    const int half = wid & 1;
    const int pair = wid >> 1;
    const int htid = pair * 32 + lane;
    const int b    = blockIdx.y;
    const int q0   = blockIdx.x * BQ;
    const int r0   = pair * 16;
    const int k0   = half * 2048;

    const int lt = lane >> 3, lr = lane & 7;
    const uint32_t aoff = (uint32_t)((r0 + ((lt & 1) << 3) + lr) * 144 + ((lt >> 1) << 4));
    const uint32_t boff = (uint32_t)((((lane >> 4) << 3) + lr) * 144 + ((lt & 1) << 4));

    const uint32_t bON = (g == 0) ? 0x3C003C00u : 0u;

    {
        const __half* qh = g_qh + ((size_t)(b * SEQ + q0)) * DOUT;
        const __half* ql = g_ql + ((size_t)(b * SEQ + q0)) * DOUT;
#pragma unroll
        for (int i = 0; i < 2; i++) {
            const int id = tid + i * 512;
            const int row = id >> 3, c = id & 7;
            cp16(smb + QH_B + row * 144 + c * 16, qh + row * DOUT + c * 8);
            cp16(smb + QL_B + row * 144 + c * 16, ql + row * DOUT + c * 8);
        }
        CP_COMMIT();
        load_kv_h(smb + KV_B(half, 0), b, k0, htid);
        CP_COMMIT();
        load_kv_h(smb + KV_B(half, 1), b, k0 + BK, htid);
        CP_COMMIT();
    }
    CP_WAIT2();
    __syncthreads();

    float o[8][4], oL[4];
#pragma unroll
    for (int j = 0; j < 8; j++)
#pragma unroll
        for (int k = 0; k < 4; k++) o[j][k] = 0.f;
#pragma unroll
    for (int k = 0; k < 4; k++) oL[k] = 0.f;
    float m0 = -3.0e38f, m1 = -3.0e38f;

    for (int t = 0; t < NTILES; t++) {
        CP_WAIT1();
        BARG(1 + half);
        if (t + 2 < NTILES)
            load_kv_h(smb + KV_B(half, (t + 2) % 3), b, k0 + (t + 2) * BK, htid);
        CP_COMMIT();

        const uint32_t kvb = smb + KV_B(half, t % 3);
        const uint32_t khb = kvb + KH_O + boff;
        const uint32_t klb = kvb + KL_O + boff;
        const uint32_t vtb = kvb + VT_O + boff;

        float s[8][4];
#pragma unroll
        for (int j = 0; j < 8; j++)
#pragma unroll
            for (int k = 0; k < 4; k++) s[j][k] = 0.f;

#pragma unroll
        for (int ks = 0; ks < 4; ks++) {
            uint32_t ah0, ah1, ah2, ah3, al0, al1, al2, al3;
            LDMX4(ah0, ah1, ah2, ah3, smb + QH_B + aoff + ks * 32);
            LDMX4(al0, al1, al2, al3, smb + QL_B + aoff + ks * 32);
#pragma unroll
            for (int jp = 0; jp < 4; jp++) {
                uint32_t bh0, bh1, bh2, bh3, bl0, bl1, bl2, bl3;
                LDMX4(bh0, bh1, bh2, bh3, khb + jp * 2304 + ks * 32);
                LDMX4(bl0, bl1, bl2, bl3, klb + jp * 2304 + ks * 32);
                MMA16816(s[2*jp],   ah0, ah1, ah2, ah3, bh0, bh1);
                MMA16816(s[2*jp+1], ah0, ah1, ah2, ah3, bh2, bh3);
                MMA16816(s[2*jp],   ah0, ah1, ah2, ah3, bl0, bl1);
                MMA16816(s[2*jp+1], ah0, ah1, ah2, ah3, bl2, bl3);
                MMA16816(s[2*jp],   al0, al1, al2, al3, bh0, bh1);
                MMA16816(s[2*jp+1], al0, al1, al2, al3, bh2, bh3);
            }
        }

        float mx0 = -3.0e38f, mx1 = -3.0e38f;
#pragma unroll
        for (int j = 0; j < 8; j++) {
            mx0 = fmaxf(mx0, fmaxf(s[j][0], s[j][1]));
            mx1 = fmaxf(mx1, fmaxf(s[j][2], s[j][3]));
        }
        mx0 = fmaxf(mx0, __shfl_xor_sync(0xffffffffu, mx0, 1));
        mx0 = fmaxf(mx0, __shfl_xor_sync(0xffffffffu, mx0, 2));
        mx1 = fmaxf(mx1, __shfl_xor_sync(0xffffffffu, mx1, 1));
        mx1 = fmaxf(mx1, __shfl_xor_sync(0xffffffffu, mx1, 2));

        const bool active = __any_sync(0xffffffffu,
                                       (mx0 > m0 - 25.f) | (mx1 > m1 - 25.f));
        if (!active) continue;

        const float mn0 = fmaxf(m0, mx0), mn1 = fmaxf(m1, mx1);
        const bool upd = __any_sync(0xffffffffu, (mx0 > m0) | (mx1 > m1));
        if (upd) {
            const float c0 = ex2f(m0 - mn0), c1 = ex2f(m1 - mn1);
#pragma unroll
            for (int j = 0; j < 8; j++) {
                o[j][0] *= c0; o[j][1] *= c0;
                o[j][2] *= c1; o[j][3] *= c1;
            }
            oL[0] *= c0; oL[1] *= c0;
            oL[2] *= c1; oL[3] *= c1;
            m0 = mn0; m1 = mn1;
        }

        uint32_t pa[4][4];
#pragma unroll
        for (int j = 0; j < 8; j++) {
            const float e0 = ex2f(s[j][0] - m0), e1 = ex2f(s[j][1] - m0);
            const float e2 = ex2f(s[j][2] - m1), e3 = ex2f(s[j][3] - m1);
            const __half2 h01 = __floats2half2_rn(e0, e1);
            const __half2 h23 = __floats2half2_rn(e2, e3);
            pa[j >> 1][(j & 1) * 2 + 0] = *(const uint32_t*)&h01;
            pa[j >> 1][(j & 1) * 2 + 1] = *(const uint32_t*)&h23;
        }

#pragma unroll
        for (int ks = 0; ks < 4; ks++) {
#pragma unroll
            for (int jp = 0; jp < 4; jp++) {
                uint32_t v0, v1, v2, v3;
                LDMX4(v0, v1, v2, v3, vtb + jp * 2304 + ks * 32);
                MMA16816(o[2*jp],   pa[ks][0], pa[ks][1], pa[ks][2], pa[ks][3], v0, v1);
                MMA16816(o[2*jp+1], pa[ks][0], pa[ks][1], pa[ks][2], pa[ks][3], v2, v3);
            }
            MMA16816(oL, pa[ks][0], pa[ks][1], pa[ks][2], pa[ks][3], bON, bON);
        }
    }

    const int qlead = lane & ~3;
    const float l0 = __shfl_sync(0xffffffffu, oL[0], qlead);
    const float l1 = __shfl_sync(0xffffffffu, oL[2], qlead);

    __syncthreads();
    float* xo = (float*)sm;
    float* xm = (float*)(sm + 8 * 16 * 68 * 4);

    if (half == 1) {
#pragma unroll
        for (int j = 0; j < 8; j++) {
            const int col = j * 8 + 2 * tq;
            *(float2*)&xo[(r0 + g) * 68 + col]     = make_float2(o[j][0], o[j][1]);
            *(float2*)&xo[(r0 + g + 8) * 68 + col] = make_float2(o[j][2], o[j][3]);
        }
        if (tq == 0) {
            xm[(r0 + g) * 2]         = m0;  xm[(r0 + g) * 2 + 1]     = l0;
            xm[(r0 + g + 8) * 2]     = m1;  xm[(r0 + g + 8) * 2 + 1] = l1;
        }
    }
    __syncthreads();

    if (half == 0) {
        const float mo0 = xm[(r0 + g) * 2],     lo0 = xm[(r0 + g) * 2 + 1];
        const float mo1 = xm[(r0 + g + 8) * 2], lo1 = xm[(r0 + g + 8) * 2 + 1];
        const float mm0 = fmaxf(m0, mo0), mm1 = fmaxf(m1, mo1);
        const float ce0 = ex2f(m0 - mm0), co0 = ex2f(mo0 - mm0);
        const float ce1 = ex2f(m1 - mm1), co1 = ex2f(mo1 - mm1);
        const float rl0 = __frcp_rn(l0 * ce0 + lo0 * co0);
        const float rl1 = __frcp_rn(l1 * ce1 + lo1 * co1);

        float* O = out + ((size_t)(b * SEQ + q0 + r0 + g)) * DOUT;
#pragma unroll
        for (int j = 0; j < 8; j++) {
            const int col = j * 8 + 2 * tq;
            const float2 q0v = *(const float2*)&xo[(r0 + g) * 68 + col];
            const float2 q1v = *(const float2*)&xo[(r0 + g + 8) * 68 + col];
            *(float2*)&O[col] = make_float2(
                (o[j][0] * ce0 + q0v.x * co0) * rl0,
                (o[j][1] * ce0 + q0v.y * co0) * rl0);
            *(float2*)&O[8 * DOUT + col] = make_float2(
                (o[j][2] * ce1 + q1v.x * co1) * rl1,
                (o[j][3] * ce1 + q1v.y * co1) * rl1);
        }
    }
}

// ---------------------------------------------------------------------------
extern "C" void kernel_launch(void* const* d_in, const int* in_sizes, int n_in,
                              void* d_out, int out_size) {
    const float* x = (const float*)d_in[0];   // [4,4096,128]
    const float* w = (const float*)d_in[1];   // [3,128,64]
    float* out = (float*)d_out;               // [4,4096,64]

    cudaFuncSetAttribute(attn_kernel,
                         cudaFuncAttributeMaxDynamicSharedMemorySize, SMEM_BYTES);
    cudaFuncSetAttribute(qkv_proj_kernel,
                         cudaFuncAttributeMaxDynamicSharedMemorySize, QKV_SMEM);

    qkv_proj_kernel<<<dim3(SEQ / 128, BATCH), 512, QKV_SMEM>>>(x, w);
    attn_kernel<<<dim3(SEQ / BQ, BATCH), 512, SMEM_BYTES>>>(out);
}